// round 7
// baseline (speedup 1.0000x reference)
#include <cuda_runtime.h>

// ---------------------------------------------------------------------------
// B=8, H=W=256, I_DIM=64, K_DIM=64/stream, V_DIM=32/stream, NH=2 (hd_k=32, hd_v=16)
// unfold(256, P=7, NK=4) -> p=7, stride=21, dilation=4, nk=12
// => 144 patches of 49 px; positions {21i+4j} all distinct per dim
// => fold has no overlap; attn writes exactly Sh x Sw, fill writes the rest.
// f32x2 packed fp32 FMA; weights in __constant__ (LDC/LDCU port, off L1tex).
// ---------------------------------------------------------------------------

#define BDIM 512           // 16 warps
#define N_ATTN 1152        // 8 batches * 144 patches
#define N_FILL 2048        // fill blocks (8 float4 per thread)

typedef unsigned long long u64;

#define FFMA2(acc, a, b) asm("fma.rn.f32x2 %0, %1, %2, %0;" : "+l"(acc) : "l"(a), "l"(b))
#define DUP2(d, v)       asm("mov.b64 %0, {%1, %1};"        : "=l"(d)   : "f"(v))
#define PACK2(d, lo, hi) asm("mov.b64 %0, {%1, %2};"        : "=l"(d)   : "f"(lo), "f"(hi))
#define UNPACK2(lo, hi, d) asm("mov.b64 {%0, %1}, %2;"      : "=f"(lo), "=f"(hi) : "l"(d))

// Packed weight-pair staging buffers (lo = even output channel, hi = odd).
__device__ __align__(16) u64 gWk2[2 * 32 * 64];   // (st*32 + qp)*64 + c
__device__ __align__(16) u64 gWv2[2 * 16 * 64];   // (st*16 + qp)*64 + c
__device__ __align__(16) u64 gWp2[32 * 64];       // cp*64 + i

// Constant-space copies: 32KB + 16KB + 16KB = 64KB (device limit, exact fit).
__constant__ u64 cWk2[2 * 32 * 64];
__constant__ u64 cWv2[2 * 16 * 64];
__constant__ u64 cWp2[32 * 64];

__global__ void repack_kernel(const float* __restrict__ Wk, const float* __restrict__ Wv,
                              const float* __restrict__ Wp) {
    int t = blockIdx.x * blockDim.x + threadIdx.x;
    int nt = gridDim.x * blockDim.x;
    for (int i = t; i < 4096; i += nt) {            // Wk pairs
        int c = i & 63, qp = (i >> 6) & 31, st = i >> 11;
        u64 d; PACK2(d, Wk[(st * 64 + 2 * qp) * 64 + c], Wk[(st * 64 + 2 * qp + 1) * 64 + c]);
        gWk2[i] = d;
    }
    for (int i = t; i < 2048; i += nt) {            // Wv pairs
        int c = i & 63, qp = (i >> 6) & 15, st = i >> 10;
        u64 d; PACK2(d, Wv[(st * 32 + 2 * qp) * 64 + c], Wv[(st * 32 + 2 * qp + 1) * 64 + c]);
        gWv2[i] = d;
    }
    for (int i = t; i < 2048; i += nt) {            // Wp pairs
        int ic = i & 63, cp = i >> 6;
        u64 d; PACK2(d, Wp[(2 * cp) * 64 + ic], Wp[(2 * cp + 1) * 64 + ic]);
        gWp2[i] = d;
    }
}

// ---- smem layout (float offsets) ----
constexpr int oX   = 0;
constexpr int oE   = 0;                  // E[(n*49+x)*52 + y]
constexpr int oET  = 5096;               // ET[(n*49+y)*52 + x]
constexpr int oA_SZ = 10192;
constexpr int oK   = oA_SZ;              // K[(st*49+p)*68 + c]
constexpr int oOT  = oA_SZ;              // OT[p*68 + i]
constexpr int oOut = oA_SZ + 3332;       // Out[c*49 + p]
constexpr int oV   = oA_SZ + 6664;       // V[(st*49+p)*36 + d], 98 rows + 4 pad rows
constexpr int oCS  = oV + 102 * 36;      // 98 (1/colsum)
constexpr int oRS  = oCS + 98;           // 98 (1/rowsum)
constexpr int SMEMF = oRS + 98;
constexpr int SMEM_BYTES = SMEMF * 4;    // 82896 bytes -> 2 CTAs/SM

// v in [0,256) is sampled iff v = 21*i + 4*j, i<12, j<7. 21 ≡ 1 (mod 4).
__device__ __forceinline__ bool is_sampled(int v) {
    int i = v & 3;
#pragma unroll
    for (int t = 0; t < 3; t++, i += 4) {
        int d = v - 21 * i;
        if (i < 12 && d >= 0 && d <= 24) return true;
    }
    return false;
}

__global__ void __launch_bounds__(BDIM, 2)
fused_kernel(const float* __restrict__ x1, const float* __restrict__ x2,
             const float* __restrict__ Wk, const float* __restrict__ bk,
             const float* __restrict__ Wv, const float* __restrict__ bv,
             const float* __restrict__ Wp, const float* __restrict__ bp,
             float* __restrict__ out) {
    // ======================= FILL PATH ===================
    if (blockIdx.x >= N_ATTN) {
        unsigned g = (blockIdx.x - N_ATTN) * BDIM + threadIdx.x;
#pragma unroll
        for (int k = 0; k < 8; k++) {
            unsigned i = g + k * (N_FILL * BDIM);
            int w4 = (i & 63) << 2;
            int h  = (i >> 6) & 255;
            int c  = (i >> 14) & 63;
            float v = __ldg(&bp[c]);
            if (!is_sampled(h)) {
                reinterpret_cast<float4*>(out)[i] = make_float4(v, v, v, v);
            } else {
                float* o = out + (size_t)i * 4;
#pragma unroll
                for (int q = 0; q < 4; q++)
                    if (!is_sampled(w4 + q)) o[q] = v;
            }
        }
        return;
    }

    // ======================= ATTENTION PATH =================================
    extern __shared__ __align__(16) float sm[];
    const int tid  = threadIdx.x;
    const int lane = tid & 31;
    const int wid  = tid >> 5;
    const bool has1 = (lane < 17);

    const int b  = blockIdx.x / 144;
    const int s  = blockIdx.x % 144;
    const int si = s / 12, sj = s % 12;

    // ---- Phase 1: gather x1/x2 at the 49 patch pixels ----
    for (int idx = tid; idx < 2 * 64 * 49; idx += BDIM) {
        int st = idx / 3136;
        int r  = idx % 3136;
        int c  = r / 49;
        int p  = r % 49;
        int px = p / 7, py = p % 7;
        int h = si * 21 + px * 4, w = sj * 21 + py * 4;
        const float* xp = st ? x2 : x1;
        sm[oX + (st * 49 + p) * 68 + c] = __ldg(&xp[((b * 64 + c) * 256 + h) * 256 + w]);
    }
    __syncthreads();

    // ---- Phase 2: 1x1 convs with packed f32x2 FMA; weights via constant port ----
    {
        const int st  = wid >> 3;
        const int sub = wid & 7;
        const float4* xa = reinterpret_cast<const float4*>(&sm[oX + (st * 49 + lane) * 68]);
        const float4* xb = reinterpret_cast<const float4*>(&sm[oX + (st * 49 + lane + 32) * 68]);

        // --------- K subtask: 4 oc-pairs ---------
        {
            int pp0 = sub * 4;
            const int wb = (st * 32 + pp0) * 64;      // u64 index into cWk2
            u64 acc[4][2];
#pragma unroll
            for (int qp = 0; qp < 4; qp++) {
                u64 bb; PACK2(bb, __ldg(&bk[st * 64 + 2 * (pp0 + qp)]),
                                  __ldg(&bk[st * 64 + 2 * (pp0 + qp) + 1]));
                acc[qp][0] = bb; acc[qp][1] = bb;
            }
#pragma unroll
            for (int i4 = 0; i4 < 16; i4++) {
                float4 a = xa[i4];
                float4 bx = has1 ? xb[i4] : make_float4(0.f, 0.f, 0.f, 0.f);
                u64 da[4], db[4];
                DUP2(da[0], a.x); DUP2(da[1], a.y); DUP2(da[2], a.z); DUP2(da[3], a.w);
                DUP2(db[0], bx.x); DUP2(db[1], bx.y); DUP2(db[2], bx.z); DUP2(db[3], bx.w);
#pragma unroll
                for (int qp = 0; qp < 4; qp++) {
                    u64 w0 = cWk2[wb + qp * 64 + i4 * 4 + 0];
                    u64 w1 = cWk2[wb + qp * 64 + i4 * 4 + 1];
                    u64 w2 = cWk2[wb + qp * 64 + i4 * 4 + 2];
                    u64 w3 = cWk2[wb + qp * 64 + i4 * 4 + 3];
                    FFMA2(acc[qp][0], w0, da[0]); FFMA2(acc[qp][0], w1, da[1]);
                    FFMA2(acc[qp][0], w2, da[2]); FFMA2(acc[qp][0], w3, da[3]);
                    FFMA2(acc[qp][1], w0, db[0]); FFMA2(acc[qp][1], w1, db[1]);
                    FFMA2(acc[qp][1], w2, db[2]); FFMA2(acc[qp][1], w3, db[3]);
                }
            }
            int oc0 = pp0 * 2;
            int ob0 = oK + (st * 49 + lane) * 68 + oc0;
            int ob1 = oK + (st * 49 + lane + 32) * 68 + oc0;
#pragma unroll
            for (int g = 0; g < 2; g++) {
                float q0, q1, q2, q3;
                UNPACK2(q0, q1, acc[2 * g][0]); UNPACK2(q2, q3, acc[2 * g + 1][0]);
                *reinterpret_cast<float4*>(&sm[ob0 + g * 4]) = make_float4(q0, q1, q2, q3);
                if (has1) {
                    UNPACK2(q0, q1, acc[2 * g][1]); UNPACK2(q2, q3, acc[2 * g + 1][1]);
                    *reinterpret_cast<float4*>(&sm[ob1 + g * 4]) = make_float4(q0, q1, q2, q3);
                }
            }
        }

        // --------- V subtask: 2 oc-pairs ---------
        {
            int vp0 = sub * 2;
            const int wb = (st * 16 + vp0) * 64;      // u64 index into cWv2
            u64 acc[2][2];
#pragma unroll
            for (int qp = 0; qp < 2; qp++) {
                u64 bb; PACK2(bb, __ldg(&bv[st * 32 + 2 * (vp0 + qp)]),
                                  __ldg(&bv[st * 32 + 2 * (vp0 + qp) + 1]));
                acc[qp][0] = bb; acc[qp][1] = bb;
            }
#pragma unroll
            for (int i4 = 0; i4 < 16; i4++) {
                float4 a = xa[i4];
                float4 bx = has1 ? xb[i4] : make_float4(0.f, 0.f, 0.f, 0.f);
                u64 da[4], db[4];
                DUP2(da[0], a.x); DUP2(da[1], a.y); DUP2(da[2], a.z); DUP2(da[3], a.w);
                DUP2(db[0], bx.x); DUP2(db[1], bx.y); DUP2(db[2], bx.z); DUP2(db[3], bx.w);
#pragma unroll
                for (int qp = 0; qp < 2; qp++) {
                    u64 w0 = cWv2[wb + qp * 64 + i4 * 4 + 0];
                    u64 w1 = cWv2[wb + qp * 64 + i4 * 4 + 1];
                    u64 w2 = cWv2[wb + qp * 64 + i4 * 4 + 2];
                    u64 w3 = cWv2[wb + qp * 64 + i4 * 4 + 3];
                    FFMA2(acc[qp][0], w0, da[0]); FFMA2(acc[qp][0], w1, da[1]);
                    FFMA2(acc[qp][0], w2, da[2]); FFMA2(acc[qp][0], w3, da[3]);
                    FFMA2(acc[qp][1], w0, db[0]); FFMA2(acc[qp][1], w1, db[1]);
                    FFMA2(acc[qp][1], w2, db[2]); FFMA2(acc[qp][1], w3, db[3]);
                }
            }
            int oc0 = vp0 * 2;
            int ob0 = oV + (st * 49 + lane) * 36 + oc0;
            int ob1 = oV + (st * 49 + lane + 32) * 36 + oc0;
            float q0, q1, q2, q3;
            UNPACK2(q0, q1, acc[0][0]); UNPACK2(q2, q3, acc[1][0]);
            *reinterpret_cast<float4*>(&sm[ob0]) = make_float4(q0, q1, q2, q3);
            if (has1) {
                UNPACK2(q0, q1, acc[0][1]); UNPACK2(q2, q3, acc[1][1]);
                *reinterpret_cast<float4*>(&sm[ob1]) = make_float4(q0, q1, q2, q3);
            }
        }
    }
    __syncthreads();

    // ---- Phase 3a: zero padding (E/ET cols 49..51; V pad rows 98..101) ----
    for (int idx = tid; idx < 588; idx += BDIM) {
        int reg = idx / 294;
        int r   = (idx % 294) / 3;
        int cc  = 49 + (idx % 3);
        sm[(reg ? oET : oE) + r * 52 + cc] = 0.f;
    }
    for (int idx = tid; idx < 4 * 36; idx += BDIM) sm[oV + 98 * 36 + idx] = 0.f;

    // ---- Phase 3b: E = exp(scale * k1 . k2), plus transposed copy ET ----
    const float SCALE = 0.17677669529663687f;   // 1/sqrt(32)
    for (int t = wid; t < 26; t += 16) {
        int n = t / 13, xg = t % 13;
        int x0 = xg * 4;
        float acc[4][2] = {};
        const float4* k2a = reinterpret_cast<const float4*>(&sm[oK + (49 + lane) * 68 + n * 32]);
        const float4* k2b = reinterpret_cast<const float4*>(&sm[oK + (49 + lane + 32) * 68 + n * 32]);
#pragma unroll
        for (int c4 = 0; c4 < 8; c4++) {
            float4 e0 = k2a[c4];
            float4 e1 = has1 ? k2b[c4] : make_float4(0.f, 0.f, 0.f, 0.f);
#pragma unroll
            for (int xx = 0; xx < 4; xx++) {
                float4 k1 = *reinterpret_cast<const float4*>(
                    &sm[oK + (x0 + xx) * 68 + n * 32 + c4 * 4]);        // broadcast
                acc[xx][0] += k1.x * e0.x + k1.y * e0.y + k1.z * e0.z + k1.w * e0.w;
                acc[xx][1] += k1.x * e1.x + k1.y * e1.y + k1.z * e1.z + k1.w * e1.w;
            }
        }
#pragma unroll
        for (int xx = 0; xx < 4; xx++) {
            int x = x0 + xx;
            if (x < 49) {
                float v0 = __expf(acc[xx][0] * SCALE);
                sm[oE + (n * 49 + x) * 52 + lane] = v0;
                sm[oET + (n * 49 + lane) * 52 + x] = v0;
                if (has1) {
                    float v1 = __expf(acc[xx][1] * SCALE);
                    sm[oE + (n * 49 + x) * 52 + lane + 32] = v1;
                    sm[oET + (n * 49 + lane + 32) * 52 + x] = v1;
                }
            }
        }
    }
    __syncthreads();

    // ---- Phase 4: reciprocal column / row sums ----
    for (int idx = tid; idx < 196; idx += BDIM) {
        int half = idx / 98;
        int r = idx % 98;
        const float4* row = reinterpret_cast<const float4*>(&sm[(half ? oE : oET) + r * 52]);
        float ssum = 0.f;
#pragma unroll
        for (int j4 = 0; j4 < 13; j4++) {
            float4 e = row[j4];
            ssum += e.x + e.y + e.z + e.w;
        }
        sm[(half ? oRS : oCS) + r] = 1.f / ssum;
    }
    __syncthreads();

    // ---- Phase 5: o1 / o2 -> OT[p][i] via packed V pairs; 16 warp-tasks ----
    {
        int which = wid >> 3;
        int n  = (wid >> 2) & 1;
        int dg = wid & 3;
        u64 acc[2][2] = {{0ull, 0ull}, {0ull, 0ull}};
        int erow0 = (which ? oE : oET) + (n * 49 + lane) * 52;
        int erow1 = (which ? oE : oET) + (n * 49 + lane + 32) * 52;
        int vbase = oV + which * 49 * 36 + n * 16 + dg * 4;
#pragma unroll
        for (int k4 = 0; k4 < 13; k4++) {
            float4 e0 = *reinterpret_cast<const float4*>(&sm[erow0 + k4 * 4]);
            float4 e1 = has1 ? *reinterpret_cast<const float4*>(&sm[erow1 + k4 * 4])
                             : make_float4(0.f, 0.f, 0.f, 0.f);
            float ea[4] = {e0.x, e0.y, e0.z, e0.w};
            float eb[4] = {e1.x, e1.y, e1.z, e1.w};
#pragma unroll
            for (int k = 0; k < 4; k++) {
                ulonglong2 v2 = *reinterpret_cast<const ulonglong2*>(&sm[vbase + (k4 * 4 + k) * 36]);
                u64 d0, d1;
                DUP2(d0, ea[k]); DUP2(d1, eb[k]);
                FFMA2(acc[0][0], v2.x, d0); FFMA2(acc[1][0], v2.y, d0);
                FFMA2(acc[0][1], v2.x, d1); FFMA2(acc[1][1], v2.y, d1);
            }
        }
        int fbase = (which ? oRS : oCS) + n * 49;
        float f0 = sm[fbase + lane];
        float f1 = has1 ? sm[fbase + lane + 32] : 0.f;
        int col = which * 32 + n * 16 + dg * 4;
        float a0, a1, a2, a3;
        UNPACK2(a0, a1, acc[0][0]); UNPACK2(a2, a3, acc[1][0]);
        *reinterpret_cast<float4*>(&sm[oOT + lane * 68 + col]) =
            make_float4(a0 * f0, a1 * f0, a2 * f0, a3 * f0);
        if (has1) {
            UNPACK2(a0, a1, acc[0][1]); UNPACK2(a2, a3, acc[1][1]);
            *reinterpret_cast<float4*>(&sm[oOT + (lane + 32) * 68 + col]) =
                make_float4(a0 * f1, a1 * f1, a2 * f1, a3 * f1);
        }
    }
    __syncthreads();

    // ---- Phase 6: Out[c][p] = bp[c] + sum_i OT[p][i] * Wp[c][i]; constant Wp pairs ----
    {
        int c0 = wid * 4;
        int cp0 = wid * 2;
        u64 acc[2][2];
#pragma unroll
        for (int j = 0; j < 2; j++) {
            u64 bb; PACK2(bb, __ldg(&bp[c0 + 2 * j]), __ldg(&bp[c0 + 2 * j + 1]));
            acc[j][0] = bb; acc[j][1] = bb;
        }
        const int wb = cp0 * 64;
#pragma unroll
        for (int i4 = 0; i4 < 16; i4++) {
            float4 oa = *reinterpret_cast<const float4*>(&sm[oOT + lane * 68 + i4 * 4]);
            float4 ob = has1 ? *reinterpret_cast<const float4*>(&sm[oOT + (lane + 32) * 68 + i4 * 4])
                             : make_float4(0.f, 0.f, 0.f, 0.f);
            u64 da[4], db[4];
            DUP2(da[0], oa.x); DUP2(da[1], oa.y); DUP2(da[2], oa.z); DUP2(da[3], oa.w);
            DUP2(db[0], ob.x); DUP2(db[1], ob.y); DUP2(db[2], ob.z); DUP2(db[3], ob.w);
#pragma unroll
            for (int j = 0; j < 2; j++) {
                u64 w0 = cWp2[wb + j * 64 + i4 * 4 + 0];
                u64 w1 = cWp2[wb + j * 64 + i4 * 4 + 1];
                u64 w2 = cWp2[wb + j * 64 + i4 * 4 + 2];
                u64 w3 = cWp2[wb + j * 64 + i4 * 4 + 3];
                FFMA2(acc[j][0], w0, da[0]); FFMA2(acc[j][0], w1, da[1]);
                FFMA2(acc[j][0], w2, da[2]); FFMA2(acc[j][0], w3, da[3]);
                FFMA2(acc[j][1], w0, db[0]); FFMA2(acc[j][1], w1, db[1]);
                FFMA2(acc[j][1], w2, db[2]); FFMA2(acc[j][1], w3, db[3]);
            }
        }
        float q0, q1, q2, q3;
        UNPACK2(q0, q1, acc[0][0]); UNPACK2(q2, q3, acc[1][0]);
        sm[oOut + (c0 + 0) * 49 + lane] = q0;
        sm[oOut + (c0 + 1) * 49 + lane] = q1;
        sm[oOut + (c0 + 2) * 49 + lane] = q2;
        sm[oOut + (c0 + 3) * 49 + lane] = q3;
        if (has1) {
            UNPACK2(q0, q1, acc[0][1]); UNPACK2(q2, q3, acc[1][1]);
            sm[oOut + (c0 + 0) * 49 + lane + 32] = q0;
            sm[oOut + (c0 + 1) * 49 + lane + 32] = q1;
            sm[oOut + (c0 + 2) * 49 + lane + 32] = q2;
            sm[oOut + (c0 + 3) * 49 + lane + 32] = q3;
        }
    }
    __syncthreads();

    // ---- Phase 7: scatter stores ----
    for (int idx = tid; idx < 64 * 49; idx += BDIM) {
        int c = idx / 49;
        int p = idx % 49;
        int px = p / 7, py = p % 7;
        int h = si * 21 + px * 4, w = sj * 21 + py * 4;
        out[((b * 64 + c) * 256 + h) * 256 + w] = sm[oOut + idx];
    }
}

extern "C" void kernel_launch(void* const* d_in, const int* in_sizes, int n_in,
                              void* d_out, int out_size) {
    const float* x1 = (const float*)d_in[0];
    const float* x2 = (const float*)d_in[1];
    const float* Wk = (const float*)d_in[2];
    const float* bk = (const float*)d_in[3];
    const float* Wv = (const float*)d_in[4];
    const float* bv = (const float*)d_in[5];
    const float* Wp = (const float*)d_in[6];
    const float* bp = (const float*)d_in[7];
    float* out = (float*)d_out;

    repack_kernel<<<32, 256>>>(Wk, Wv, Wp);

    // Stage packed weights into constant memory (device-to-device async copies,
    // graph-capturable; ordered after repack on the same stream).
    void* src;
    cudaGetSymbolAddress(&src, gWk2);
    cudaMemcpyToSymbolAsync(cWk2, src, sizeof(gWk2), 0, cudaMemcpyDeviceToDevice, 0);
    cudaGetSymbolAddress(&src, gWv2);
    cudaMemcpyToSymbolAsync(cWv2, src, sizeof(gWv2), 0, cudaMemcpyDeviceToDevice, 0);
    cudaGetSymbolAddress(&src, gWp2);
    cudaMemcpyToSymbolAsync(cWp2, src, sizeof(gWp2), 0, cudaMemcpyDeviceToDevice, 0);

    cudaFuncSetAttribute(fused_kernel,
                         cudaFuncAttributeMaxDynamicSharedMemorySize, SMEM_BYTES);
    fused_kernel<<<N_ATTN + N_FILL, BDIM, SMEM_BYTES>>>(x1, x2, Wk, bk, Wv, bv, Wp, bp, out);
}

// round 8
// speedup vs baseline: 5.0775x; 5.0775x over previous
#include <cuda_runtime.h>

// ---------------------------------------------------------------------------
// B=8, H=W=256, I_DIM=64, K_DIM=64/stream, V_DIM=32/stream, NH=2 (hd_k=32, hd_v=16)
// unfold(256, P=7, NK=4) -> p=7, stride=21, dilation=4, nk=12
// => 144 patches of 49 px; positions {21i+4j} all distinct per dim
// => fold has no overlap; attn writes exactly Sh x Sw, fill writes the rest.
// f32x2 packed fp32 FMA; packed weights via __ldg (L1-resident broadcasts).
// One 1024-thread CTA = 2 patches: weight loads amortized across both.
// ---------------------------------------------------------------------------

#define BDIM 1024          // 32 warps, 2 patches per CTA
#define N_ATTN 576         // 1152 patches / 2
#define N_FILL 1024        // fill blocks (8 float4 per thread @1024 thr)

typedef unsigned long long u64;

#define FFMA2(acc, a, b) asm("fma.rn.f32x2 %0, %1, %2, %0;" : "+l"(acc) : "l"(a), "l"(b))
#define DUP2(d, v)       asm("mov.b64 %0, {%1, %1};"        : "=l"(d)   : "f"(v))
#define PACK2(d, lo, hi) asm("mov.b64 %0, {%1, %2};"        : "=l"(d)   : "f"(lo), "f"(hi))
#define UNPACK2(lo, hi, d) asm("mov.b64 {%0, %1}, %2;"      : "=f"(lo), "=f"(hi) : "l"(d))

// Packed weight-pair buffers (lo = even output channel, hi = odd).
__device__ __align__(16) u64 gWk2[2 * 32 * 64];   // (st*32 + qp)*64 + c
__device__ __align__(16) u64 gWv2[2 * 16 * 64];   // (st*16 + qp)*64 + c
__device__ __align__(16) u64 gWp2[32 * 64];       // cp*64 + i

__global__ void repack_kernel(const float* __restrict__ Wk, const float* __restrict__ Wv,
                              const float* __restrict__ Wp) {
    int t = blockIdx.x * blockDim.x + threadIdx.x;
    int nt = gridDim.x * blockDim.x;
    for (int i = t; i < 4096; i += nt) {            // Wk pairs
        int c = i & 63, qp = (i >> 6) & 31, st = i >> 11;
        u64 d; PACK2(d, Wk[(st * 64 + 2 * qp) * 64 + c], Wk[(st * 64 + 2 * qp + 1) * 64 + c]);
        gWk2[i] = d;
    }
    for (int i = t; i < 2048; i += nt) {            // Wv pairs
        int c = i & 63, qp = (i >> 6) & 15, st = i >> 10;
        u64 d; PACK2(d, Wv[(st * 32 + 2 * qp) * 64 + c], Wv[(st * 32 + 2 * qp + 1) * 64 + c]);
        gWv2[i] = d;
    }
    for (int i = t; i < 2048; i += nt) {            // Wp pairs
        int ic = i & 63, cp = i >> 6;
        u64 d; PACK2(d, Wp[(2 * cp) * 64 + ic], Wp[(2 * cp + 1) * 64 + ic]);
        gWp2[i] = d;
    }
}

// ---- per-patch smem layout (float offsets within a patch slab) ----
constexpr int oX   = 0;
constexpr int oE   = 0;                  // E[(n*49+x)*52 + y]
constexpr int oET  = 5096;               // ET[(n*49+y)*52 + x]
constexpr int oA_SZ = 10192;
constexpr int oK   = oA_SZ;              // K[(st*49+p)*68 + c]
constexpr int oOT  = oA_SZ;              // OT[p*68 + i]
constexpr int oOut = oA_SZ + 3332;       // Out[c*49 + p]
constexpr int oV   = oA_SZ + 6664;       // V[(st*49+p)*36 + d], 98 rows + 4 pad rows
constexpr int oCS  = oV + 102 * 36;      // 98 (1/colsum)
constexpr int oRS  = oCS + 98;           // 98 (1/rowsum)
constexpr int SLAB = oRS + 98;           // 20724 floats per patch (82896 B, 16B-mult)
constexpr int SMEM_BYTES = 2 * SLAB * 4; // 165792 bytes -> 1 CTA/SM

// v in [0,256) is sampled iff v = 21*i + 4*j, i<12, j<7. 21 ≡ 1 (mod 4).
__device__ __forceinline__ bool is_sampled(int v) {
    int i = v & 3;
#pragma unroll
    for (int t = 0; t < 3; t++, i += 4) {
        int d = v - 21 * i;
        if (i < 12 && d >= 0 && d <= 24) return true;
    }
    return false;
}

__global__ void __launch_bounds__(BDIM, 1)
fused_kernel(const float* __restrict__ x1, const float* __restrict__ x2,
             const float* __restrict__ Wk, const float* __restrict__ bk,
             const float* __restrict__ Wv, const float* __restrict__ bv,
             const float* __restrict__ Wp, const float* __restrict__ bp,
             float* __restrict__ out) {
    // ======================= FILL PATH ===================
    if (blockIdx.x >= N_ATTN) {
        unsigned g = (blockIdx.x - N_ATTN) * BDIM + threadIdx.x;   // < 1048576
#pragma unroll
        for (int k = 0; k < 8; k++) {
            unsigned i = g + k * (N_FILL * BDIM);                  // < 8388608 float4
            int w4 = (i & 63) << 2;
            int h  = (i >> 6) & 255;
            int c  = (i >> 14) & 63;
            float v = __ldg(&bp[c]);
            if (!is_sampled(h)) {
                reinterpret_cast<float4*>(out)[i] = make_float4(v, v, v, v);
            } else {
                float* o = out + (size_t)i * 4;
#pragma unroll
                for (int q = 0; q < 4; q++)
                    if (!is_sampled(w4 + q)) o[q] = v;
            }
        }
        return;
    }

    // ======================= ATTENTION PATH (2 patches / CTA) ===============
    extern __shared__ __align__(16) float sm[];
    const int tid  = threadIdx.x;
    const int lane = tid & 31;
    const int wid  = tid >> 5;
    const bool has1 = (lane < 17);

    // per-patch geometry (patch gp = blockIdx.x*2 + pa)
    int gsi[2], gsj[2], gb[2];
#pragma unroll
    for (int pa = 0; pa < 2; pa++) {
        int gp = blockIdx.x * 2 + pa;
        gb[pa] = gp / 144;
        int s  = gp % 144;
        gsi[pa] = s / 12; gsj[pa] = s % 12;
    }

    // ---- Phase 1: gather x1/x2 at the 49 patch pixels (both patches) ----
    for (int idx = tid; idx < 2 * 2 * 64 * 49; idx += BDIM) {
        int pa = idx / 6272;
        int r0 = idx % 6272;
        int st = r0 / 3136;
        int r  = r0 % 3136;
        int c  = r / 49;
        int p  = r % 49;
        int px = p / 7, py = p % 7;
        int h = gsi[pa] * 21 + px * 4, w = gsj[pa] * 21 + py * 4;
        const float* xp = st ? x2 : x1;
        sm[pa * SLAB + oX + (st * 49 + p) * 68 + c] =
            __ldg(&xp[((gb[pa] * 64 + c) * 256 + h) * 256 + w]);
    }
    __syncthreads();

    // ---- Phase 2: 1x1 convs; weights loaded once, applied to BOTH patches ----
    {
        const int st  = wid >> 4;          // stream
        const int sub = wid & 15;

        // --------- K subtask: 2 oc-pairs, 2 halves, 2 patches ---------
        {
            int pp0 = sub * 2;
            const ulonglong2* W2 = reinterpret_cast<const ulonglong2*>(&gWk2[(st * 32 + pp0) * 64]);
            u64 acc[2][2][2];              // [qp][half][patch]
#pragma unroll
            for (int qp = 0; qp < 2; qp++) {
                u64 bb; PACK2(bb, __ldg(&bk[st * 64 + 2 * (pp0 + qp)]),
                                  __ldg(&bk[st * 64 + 2 * (pp0 + qp) + 1]));
                acc[qp][0][0] = bb; acc[qp][1][0] = bb;
                acc[qp][0][1] = bb; acc[qp][1][1] = bb;
            }
            const float4* xa0 = reinterpret_cast<const float4*>(&sm[0 * SLAB + oX + (st * 49 + lane) * 68]);
            const float4* xb0 = reinterpret_cast<const float4*>(&sm[0 * SLAB + oX + (st * 49 + lane + 32) * 68]);
            const float4* xa1 = reinterpret_cast<const float4*>(&sm[1 * SLAB + oX + (st * 49 + lane) * 68]);
            const float4* xb1 = reinterpret_cast<const float4*>(&sm[1 * SLAB + oX + (st * 49 + lane + 32) * 68]);
#pragma unroll
            for (int i4 = 0; i4 < 16; i4++) {
                ulonglong2 w0a = __ldg(&W2[0 * 32 + i4 * 2]);
                ulonglong2 w0b = __ldg(&W2[0 * 32 + i4 * 2 + 1]);
                ulonglong2 w1a = __ldg(&W2[1 * 32 + i4 * 2]);
                ulonglong2 w1b = __ldg(&W2[1 * 32 + i4 * 2 + 1]);
#pragma unroll
                for (int pa = 0; pa < 2; pa++) {
                    float4 a = pa ? xa1[i4] : xa0[i4];
                    float4 bx = has1 ? (pa ? xb1[i4] : xb0[i4]) : make_float4(0.f, 0.f, 0.f, 0.f);
                    u64 d;
                    DUP2(d, a.x);  FFMA2(acc[0][0][pa], w0a.x, d); FFMA2(acc[1][0][pa], w1a.x, d);
                    DUP2(d, a.y);  FFMA2(acc[0][0][pa], w0a.y, d); FFMA2(acc[1][0][pa], w1a.y, d);
                    DUP2(d, a.z);  FFMA2(acc[0][0][pa], w0b.x, d); FFMA2(acc[1][0][pa], w1b.x, d);
                    DUP2(d, a.w);  FFMA2(acc[0][0][pa], w0b.y, d); FFMA2(acc[1][0][pa], w1b.y, d);
                    DUP2(d, bx.x); FFMA2(acc[0][1][pa], w0a.x, d); FFMA2(acc[1][1][pa], w1a.x, d);
                    DUP2(d, bx.y); FFMA2(acc[0][1][pa], w0a.y, d); FFMA2(acc[1][1][pa], w1a.y, d);
                    DUP2(d, bx.z); FFMA2(acc[0][1][pa], w0b.x, d); FFMA2(acc[1][1][pa], w1b.x, d);
                    DUP2(d, bx.w); FFMA2(acc[0][1][pa], w0b.y, d); FFMA2(acc[1][1][pa], w1b.y, d);
                }
            }
            int oc0 = pp0 * 2;
#pragma unroll
            for (int pa = 0; pa < 2; pa++) {
                int ob0 = pa * SLAB + oK + (st * 49 + lane) * 68 + oc0;
                int ob1 = pa * SLAB + oK + (st * 49 + lane + 32) * 68 + oc0;
                float q0, q1, q2, q3;
                UNPACK2(q0, q1, acc[0][0][pa]); UNPACK2(q2, q3, acc[1][0][pa]);
                *reinterpret_cast<float4*>(&sm[ob0]) = make_float4(q0, q1, q2, q3);
                if (has1) {
                    UNPACK2(q0, q1, acc[0][1][pa]); UNPACK2(q2, q3, acc[1][1][pa]);
                    *reinterpret_cast<float4*>(&sm[ob1]) = make_float4(q0, q1, q2, q3);
                }
            }
        }

        // --------- V subtask: 1 oc-pair, 2 halves, 2 patches ---------
        {
            int vp = sub;                  // 16 pairs per stream
            const ulonglong2* W2 = reinterpret_cast<const ulonglong2*>(&gWv2[(st * 16 + vp) * 64]);
            u64 acc[2][2];                 // [half][patch]
            {
                u64 bb; PACK2(bb, __ldg(&bv[st * 32 + 2 * vp]), __ldg(&bv[st * 32 + 2 * vp + 1]));
                acc[0][0] = bb; acc[1][0] = bb; acc[0][1] = bb; acc[1][1] = bb;
            }
            const float4* xa0 = reinterpret_cast<const float4*>(&sm[0 * SLAB + oX + (st * 49 + lane) * 68]);
            const float4* xb0 = reinterpret_cast<const float4*>(&sm[0 * SLAB + oX + (st * 49 + lane + 32) * 68]);
            const float4* xa1 = reinterpret_cast<const float4*>(&sm[1 * SLAB + oX + (st * 49 + lane) * 68]);
            const float4* xb1 = reinterpret_cast<const float4*>(&sm[1 * SLAB + oX + (st * 49 + lane + 32) * 68]);
#pragma unroll
            for (int i4 = 0; i4 < 16; i4++) {
                ulonglong2 wa = __ldg(&W2[i4 * 2]);
                ulonglong2 wb = __ldg(&W2[i4 * 2 + 1]);
#pragma unroll
                for (int pa = 0; pa < 2; pa++) {
                    float4 a = pa ? xa1[i4] : xa0[i4];
                    float4 bx = has1 ? (pa ? xb1[i4] : xb0[i4]) : make_float4(0.f, 0.f, 0.f, 0.f);
                    u64 d;
                    DUP2(d, a.x);  FFMA2(acc[0][pa], wa.x, d);
                    DUP2(d, a.y);  FFMA2(acc[0][pa], wa.y, d);
                    DUP2(d, a.z);  FFMA2(acc[0][pa], wb.x, d);
                    DUP2(d, a.w);  FFMA2(acc[0][pa], wb.y, d);
                    DUP2(d, bx.x); FFMA2(acc[1][pa], wa.x, d);
                    DUP2(d, bx.y); FFMA2(acc[1][pa], wa.y, d);
                    DUP2(d, bx.z); FFMA2(acc[1][pa], wb.x, d);
                    DUP2(d, bx.w); FFMA2(acc[1][pa], wb.y, d);
                }
            }
            int oc0 = vp * 2;
#pragma unroll
            for (int pa = 0; pa < 2; pa++) {
                float q0, q1;
                UNPACK2(q0, q1, acc[0][pa]);
                *reinterpret_cast<float2*>(&sm[pa * SLAB + oV + (st * 49 + lane) * 36 + oc0]) =
                    make_float2(q0, q1);
                if (has1) {
                    UNPACK2(q0, q1, acc[1][pa]);
                    *reinterpret_cast<float2*>(&sm[pa * SLAB + oV + (st * 49 + lane + 32) * 36 + oc0]) =
                        make_float2(q0, q1);
                }
            }
        }
    }
    __syncthreads();

    // ---- Phase 3a: zero padding (E/ET cols 49..51; V pad rows), both patches ----
    for (int idx = tid; idx < 2 * 588; idx += BDIM) {
        int pa  = idx / 588;
        int r0  = idx % 588;
        int reg = r0 / 294;
        int r   = (r0 % 294) / 3;
        int cc  = 49 + (r0 % 3);
        sm[pa * SLAB + (reg ? oET : oE) + r * 52 + cc] = 0.f;
    }
    for (int idx = tid; idx < 2 * 4 * 36; idx += BDIM) {
        int pa = idx / 144;
        sm[pa * SLAB + oV + 98 * 36 + (idx % 144)] = 0.f;
    }

    // ---- Phase 3b: E = exp(scale * k1 . k2) + transposed copy; per-patch warps ----
    const float SCALE = 0.17677669529663687f;   // 1/sqrt(32)
    {
        const int pa = wid >> 4;
        const int w16 = wid & 15;
        const int base = pa * SLAB;
        for (int t = w16; t < 26; t += 16) {
            int n = t / 13, xg = t % 13;
            int x0 = xg * 4;
            float acc[4][2] = {};
            const float4* k2a = reinterpret_cast<const float4*>(&sm[base + oK + (49 + lane) * 68 + n * 32]);
            const float4* k2b = reinterpret_cast<const float4*>(&sm[base + oK + (49 + lane + 32) * 68 + n * 32]);
#pragma unroll
            for (int c4 = 0; c4 < 8; c4++) {
                float4 e0 = k2a[c4];
                float4 e1 = has1 ? k2b[c4] : make_float4(0.f, 0.f, 0.f, 0.f);
#pragma unroll
                for (int xx = 0; xx < 4; xx++) {
                    float4 k1 = *reinterpret_cast<const float4*>(
                        &sm[base + oK + (x0 + xx) * 68 + n * 32 + c4 * 4]);  // broadcast
                    acc[xx][0] += k1.x * e0.x + k1.y * e0.y + k1.z * e0.z + k1.w * e0.w;
                    acc[xx][1] += k1.x * e1.x + k1.y * e1.y + k1.z * e1.z + k1.w * e1.w;
                }
            }
#pragma unroll
            for (int xx = 0; xx < 4; xx++) {
                int x = x0 + xx;
                if (x < 49) {
                    float v0 = __expf(acc[xx][0] * SCALE);
                    sm[base + oE + (n * 49 + x) * 52 + lane] = v0;
                    sm[base + oET + (n * 49 + lane) * 52 + x] = v0;
                    if (has1) {
                        float v1 = __expf(acc[xx][1] * SCALE);
                        sm[base + oE + (n * 49 + x) * 52 + lane + 32] = v1;
                        sm[base + oET + (n * 49 + lane + 32) * 52 + x] = v1;
                    }
                }
            }
        }
    }
    __syncthreads();

    // ---- Phase 4: reciprocal column / row sums, both patches ----
    for (int idx = tid; idx < 2 * 196; idx += BDIM) {
        int pa   = idx / 196;
        int r0   = idx % 196;
        int half = r0 / 98;
        int r    = r0 % 98;
        const float4* row = reinterpret_cast<const float4*>(&sm[pa * SLAB + (half ? oE : oET) + r * 52]);
        float ssum = 0.f;
#pragma unroll
        for (int j4 = 0; j4 < 13; j4++) {
            float4 e = row[j4];
            ssum += e.x + e.y + e.z + e.w;
        }
        sm[pa * SLAB + (half ? oRS : oCS) + r] = 1.f / ssum;
    }
    __syncthreads();

    // ---- Phase 5: o1 / o2 -> OT[p][i]; 16 warp-tasks per patch ----
    {
        const int pa = wid >> 4;
        const int w16 = wid & 15;
        const int base = pa * SLAB;
        int which = w16 >> 3;
        int n  = (w16 >> 2) & 1;
        int dg = w16 & 3;
        u64 acc[2][2] = {{0ull, 0ull}, {0ull, 0ull}};
        int erow0 = base + (which ? oE : oET) + (n * 49 + lane) * 52;
        int erow1 = base + (which ? oE : oET) + (n * 49 + lane + 32) * 52;
        int vbase = base + oV + which * 49 * 36 + n * 16 + dg * 4;
#pragma unroll
        for (int k4 = 0; k4 < 13; k4++) {
            float4 e0 = *reinterpret_cast<const float4*>(&sm[erow0 + k4 * 4]);
            float4 e1 = has1 ? *reinterpret_cast<const float4*>(&sm[erow1 + k4 * 4])
                             : make_float4(0.f, 0.f, 0.f, 0.f);
            float ea[4] = {e0.x, e0.y, e0.z, e0.w};
            float eb[4] = {e1.x, e1.y, e1.z, e1.w};
#pragma unroll
            for (int k = 0; k < 4; k++) {
                ulonglong2 v2 = *reinterpret_cast<const ulonglong2*>(&sm[vbase + (k4 * 4 + k) * 36]);
                u64 d0, d1;
                DUP2(d0, ea[k]); DUP2(d1, eb[k]);
                FFMA2(acc[0][0], v2.x, d0); FFMA2(acc[1][0], v2.y, d0);
                FFMA2(acc[0][1], v2.x, d1); FFMA2(acc[1][1], v2.y, d1);
            }
        }
        int fbase = base + (which ? oRS : oCS) + n * 49;
        float f0 = sm[fbase + lane];
        float f1 = has1 ? sm[fbase + lane + 32] : 0.f;
        int col = which * 32 + n * 16 + dg * 4;
        float a0, a1, a2, a3;
        UNPACK2(a0, a1, acc[0][0]); UNPACK2(a2, a3, acc[1][0]);
        *reinterpret_cast<float4*>(&sm[base + oOT + lane * 68 + col]) =
            make_float4(a0 * f0, a1 * f0, a2 * f0, a3 * f0);
        if (has1) {
            UNPACK2(a0, a1, acc[0][1]); UNPACK2(a2, a3, acc[1][1]);
            *reinterpret_cast<float4*>(&sm[base + oOT + (lane + 32) * 68 + col]) =
                make_float4(a0 * f1, a1 * f1, a2 * f1, a3 * f1);
        }
    }
    __syncthreads();

    // ---- Phase 6: Out[c][p] = bp[c] + sum_i OT[p][i]*Wp[c][i]; Wp shared across patches ----
    {
        const int pa = wid >> 4;
        const int w16 = wid & 15;
        const int base = pa * SLAB;
        int c0 = w16 * 4;
        int cp0 = w16 * 2;
        u64 acc[2][2];
#pragma unroll
        for (int j = 0; j < 2; j++) {
            u64 bb; PACK2(bb, __ldg(&bp[c0 + 2 * j]), __ldg(&bp[c0 + 2 * j + 1]));
            acc[j][0] = bb; acc[j][1] = bb;
        }
        const ulonglong2* W2 = reinterpret_cast<const ulonglong2*>(&gWp2[cp0 * 64]);
#pragma unroll
        for (int i4 = 0; i4 < 16; i4++) {
            float4 oa = *reinterpret_cast<const float4*>(&sm[base + oOT + lane * 68 + i4 * 4]);
            float4 ob = has1 ? *reinterpret_cast<const float4*>(&sm[base + oOT + (lane + 32) * 68 + i4 * 4])
                             : make_float4(0.f, 0.f, 0.f, 0.f);
            u64 da[4], db[4];
            DUP2(da[0], oa.x); DUP2(da[1], oa.y); DUP2(da[2], oa.z); DUP2(da[3], oa.w);
            DUP2(db[0], ob.x); DUP2(db[1], ob.y); DUP2(db[2], ob.z); DUP2(db[3], ob.w);
#pragma unroll
            for (int j = 0; j < 2; j++) {
                ulonglong2 w01 = __ldg(&W2[j * 32 + i4 * 2]);
                ulonglong2 w23 = __ldg(&W2[j * 32 + i4 * 2 + 1]);
                FFMA2(acc[j][0], w01.x, da[0]); FFMA2(acc[j][0], w01.y, da[1]);
                FFMA2(acc[j][0], w23.x, da[2]); FFMA2(acc[j][0], w23.y, da[3]);
                FFMA2(acc[j][1], w01.x, db[0]); FFMA2(acc[j][1], w01.y, db[1]);
                FFMA2(acc[j][1], w23.x, db[2]); FFMA2(acc[j][1], w23.y, db[3]);
            }
        }
        float q0, q1, q2, q3;
        UNPACK2(q0, q1, acc[0][0]); UNPACK2(q2, q3, acc[1][0]);
        sm[base + oOut + (c0 + 0) * 49 + lane] = q0;
        sm[base + oOut + (c0 + 1) * 49 + lane] = q1;
        sm[base + oOut + (c0 + 2) * 49 + lane] = q2;
        sm[base + oOut + (c0 + 3) * 49 + lane] = q3;
        if (has1) {
            UNPACK2(q0, q1, acc[0][1]); UNPACK2(q2, q3, acc[1][1]);
            sm[base + oOut + (c0 + 0) * 49 + lane + 32] = q0;
            sm[base + oOut + (c0 + 1) * 49 + lane + 32] = q1;
            sm[base + oOut + (c0 + 2) * 49 + lane + 32] = q2;
            sm[base + oOut + (c0 + 3) * 49 + lane + 32] = q3;
        }
    }
    __syncthreads();

    // ---- Phase 7: scatter stores, both patches ----
    for (int idx = tid; idx < 2 * 64 * 49; idx += BDIM) {
        int pa = idx / 3136;
        int r  = idx % 3136;
        int c = r / 49;
        int p = r % 49;
        int px = p / 7, py = p % 7;
        int h = gsi[pa] * 21 + px * 4, w = gsj[pa] * 21 + py * 4;
        out[((gb[pa] * 64 + c) * 256 + h) * 256 + w] = sm[pa * SLAB + oOut + r];
    }
}

extern "C" void kernel_launch(void* const* d_in, const int* in_sizes, int n_in,
                              void* d_out, int out_size) {
    const float* x1 = (const float*)d_in[0];
    const float* x2 = (const float*)d_in[1];
    const float* Wk = (const float*)d_in[2];
    const float* bk = (const float*)d_in[3];
    const float* Wv = (const float*)d_in[4];
    const float* bv = (const float*)d_in[5];
    const float* Wp = (const float*)d_in[6];
    const float* bp = (const float*)d_in[7];
    float* out = (float*)d_out;

    repack_kernel<<<32, 256>>>(Wk, Wv, Wp);

    cudaFuncSetAttribute(fused_kernel,
                         cudaFuncAttributeMaxDynamicSharedMemorySize, SMEM_BYTES);
    fused_kernel<<<N_ATTN + N_FILL, BDIM, SMEM_BYTES>>>(x1, x2, Wk, bk, Wv, bv, Wp, bp, out);
}

// round 9
// speedup vs baseline: 5.6500x; 1.1127x over previous
#include <cuda_runtime.h>

// ---------------------------------------------------------------------------
// B=8, H=W=256, I_DIM=64, K_DIM=64/stream, V_DIM=32/stream, NH=2 (hd_k=32, hd_v=16)
// unfold(256, P=7, NK=4) -> p=7, stride=21, dilation=4, nk=12
// => 144 patches of 49 px; positions {21i+4j} all distinct per dim
// => fold has no overlap; attn writes exactly Sh x Sw, fill writes the rest.
// f32x2 packed fp32 FMA; packed weights via __ldg (L1-resident broadcasts).
// ---------------------------------------------------------------------------

#define BDIM 512           // 16 warps
#define N_ATTN 1152        // 8 batches * 144 patches
#define N_FILL 2048        // fill blocks (8 float4 per thread)

typedef unsigned long long u64;

#define FFMA2(acc, a, b) asm("fma.rn.f32x2 %0, %1, %2, %0;" : "+l"(acc) : "l"(a), "l"(b))
#define DUP2(d, v)       asm("mov.b64 %0, {%1, %1};"        : "=l"(d)   : "f"(v))
#define PACK2(d, lo, hi) asm("mov.b64 %0, {%1, %2};"        : "=l"(d)   : "f"(lo), "f"(hi))
#define UNPACK2(lo, hi, d) asm("mov.b64 {%0, %1}, %2;"      : "=f"(lo), "=f"(hi) : "l"(d))

// Packed weight-pair buffers (lo = even output channel, hi = odd).
__device__ __align__(16) u64 gWk2[2 * 32 * 64];   // (st*32 + qp)*64 + c
__device__ __align__(16) u64 gWv2[2 * 16 * 64];   // (st*16 + qp)*64 + c
__device__ __align__(16) u64 gWp2[32 * 64];       // cp*64 + i

__global__ void repack_kernel(const float* __restrict__ Wk, const float* __restrict__ Wv,
                              const float* __restrict__ Wp) {
    int t = blockIdx.x * blockDim.x + threadIdx.x;
    int nt = gridDim.x * blockDim.x;
    for (int i = t; i < 4096; i += nt) {            // Wk pairs
        int c = i & 63, qp = (i >> 6) & 31, st = i >> 11;
        u64 d; PACK2(d, Wk[(st * 64 + 2 * qp) * 64 + c], Wk[(st * 64 + 2 * qp + 1) * 64 + c]);
        gWk2[i] = d;
    }
    for (int i = t; i < 2048; i += nt) {            // Wv pairs
        int c = i & 63, qp = (i >> 6) & 15, st = i >> 10;
        u64 d; PACK2(d, Wv[(st * 32 + 2 * qp) * 64 + c], Wv[(st * 32 + 2 * qp + 1) * 64 + c]);
        gWv2[i] = d;
    }
    for (int i = t; i < 2048; i += nt) {            // Wp pairs
        int ic = i & 63, cp = i >> 6;
        u64 d; PACK2(d, Wp[(2 * cp) * 64 + ic], Wp[(2 * cp + 1) * 64 + ic]);
        gWp2[i] = d;
    }
}

// ---- smem layout (float offsets) ----
constexpr int oX   = 0;
constexpr int oE   = 0;                  // E[(n*49+x)*52 + y]
constexpr int oET  = 5096;               // ET[(n*49+y)*52 + x]
constexpr int oA_SZ = 10192;
constexpr int oK   = oA_SZ;              // K[(st*49+p)*68 + c]
constexpr int oOT  = oA_SZ;              // OT[p*68 + i]
constexpr int oOut = oA_SZ + 3332;       // Out[c*49 + p]
constexpr int oV   = oA_SZ + 6664;       // V[(st*49+p)*36 + d]  (98 rows, no pad)
constexpr int oCS  = oV + 98 * 36;       // 98 (1/colsum)
constexpr int oRS  = oCS + 98;           // 98 (1/rowsum)
constexpr int SMEMF = oRS + 98;
constexpr int SMEM_BYTES = SMEMF * 4;    // 82320 bytes -> 2 CTAs/SM

// v in [0,256) is sampled iff v = 21*i + 4*j, i<12, j<7. 21 ≡ 1 (mod 4).
__device__ __forceinline__ bool is_sampled(int v) {
    int i = v & 3;
#pragma unroll
    for (int t = 0; t < 3; t++, i += 4) {
        int d = v - 21 * i;
        if (i < 12 && d >= 0 && d <= 24) return true;
    }
    return false;
}

__global__ void __launch_bounds__(BDIM, 2)
fused_kernel(const float* __restrict__ x1, const float* __restrict__ x2,
             const float* __restrict__ Wk, const float* __restrict__ bk,
             const float* __restrict__ Wv, const float* __restrict__ bv,
             const float* __restrict__ Wp, const float* __restrict__ bp,
             float* __restrict__ out) {
    // ======================= FILL PATH ===================
    if (blockIdx.x >= N_ATTN) {
        unsigned g = (blockIdx.x - N_ATTN) * BDIM + threadIdx.x;
#pragma unroll
        for (int k = 0; k < 8; k++) {
            unsigned i = g + k * (N_FILL * BDIM);
            int w4 = (i & 63) << 2;
            int h  = (i >> 6) & 255;
            int c  = (i >> 14) & 63;
            float v = __ldg(&bp[c]);
            if (!is_sampled(h)) {
                reinterpret_cast<float4*>(out)[i] = make_float4(v, v, v, v);
            } else {
                float* o = out + (size_t)i * 4;
#pragma unroll
                for (int q = 0; q < 4; q++)
                    if (!is_sampled(w4 + q)) o[q] = v;
            }
        }
        return;
    }

    // ======================= ATTENTION PATH =================================
    extern __shared__ __align__(16) float sm[];
    const int tid  = threadIdx.x;
    const int lane = tid & 31;
    const int wid  = tid >> 5;
    const bool has1 = (lane < 17);

    const int b  = blockIdx.x / 144;
    const int s  = blockIdx.x % 144;
    const int si = s / 12, sj = s % 12;

    // ---- Phase 1: gather x1/x2 at the 49 patch pixels ----
    for (int idx = tid; idx < 2 * 64 * 49; idx += BDIM) {
        int st = idx / 3136;
        int r  = idx % 3136;
        int c  = r / 49;
        int p  = r % 49;
        int px = p / 7, py = p % 7;
        int h = si * 21 + px * 4, w = sj * 21 + py * 4;
        const float* xp = st ? x2 : x1;
        sm[oX + (st * 49 + p) * 68 + c] = __ldg(&xp[((b * 64 + c) * 256 + h) * 256 + w]);
    }
    __syncthreads();

    // ---- Phase 2: fused K+V 1x1 convs; X loaded once, DUPs shared ----
    {
        const int st  = wid >> 3;
        const int sub = wid & 7;
        const int pp0 = sub * 4;            // 4 K oc-pairs
        const int vp0 = sub * 2;            // 2 V oc-pairs
        const ulonglong2* WK2 = reinterpret_cast<const ulonglong2*>(&gWk2[(st * 32 + pp0) * 64]);
        const ulonglong2* WV2 = reinterpret_cast<const ulonglong2*>(&gWv2[(st * 16 + vp0) * 64]);
        u64 accK[4][2], accV[2][2];
#pragma unroll
        for (int qp = 0; qp < 4; qp++) {
            u64 bb; PACK2(bb, __ldg(&bk[st * 64 + 2 * (pp0 + qp)]),
                              __ldg(&bk[st * 64 + 2 * (pp0 + qp) + 1]));
            accK[qp][0] = bb; accK[qp][1] = bb;
        }
#pragma unroll
        for (int qp = 0; qp < 2; qp++) {
            u64 bb; PACK2(bb, __ldg(&bv[st * 32 + 2 * (vp0 + qp)]),
                              __ldg(&bv[st * 32 + 2 * (vp0 + qp) + 1]));
            accV[qp][0] = bb; accV[qp][1] = bb;
        }
        const float4* xa = reinterpret_cast<const float4*>(&sm[oX + (st * 49 + lane) * 68]);
        const float4* xb = reinterpret_cast<const float4*>(&sm[oX + (st * 49 + lane + 32) * 68]);
#pragma unroll
        for (int i4 = 0; i4 < 16; i4++) {
            float4 a = xa[i4];
            float4 bx = has1 ? xb[i4] : make_float4(0.f, 0.f, 0.f, 0.f);
            u64 da[4], db[4];
            DUP2(da[0], a.x); DUP2(da[1], a.y); DUP2(da[2], a.z); DUP2(da[3], a.w);
            DUP2(db[0], bx.x); DUP2(db[1], bx.y); DUP2(db[2], bx.z); DUP2(db[3], bx.w);
#pragma unroll
            for (int qp = 0; qp < 4; qp++) {
                ulonglong2 w01 = __ldg(&WK2[qp * 32 + i4 * 2]);
                ulonglong2 w23 = __ldg(&WK2[qp * 32 + i4 * 2 + 1]);
                FFMA2(accK[qp][0], w01.x, da[0]); FFMA2(accK[qp][0], w01.y, da[1]);
                FFMA2(accK[qp][0], w23.x, da[2]); FFMA2(accK[qp][0], w23.y, da[3]);
                FFMA2(accK[qp][1], w01.x, db[0]); FFMA2(accK[qp][1], w01.y, db[1]);
                FFMA2(accK[qp][1], w23.x, db[2]); FFMA2(accK[qp][1], w23.y, db[3]);
            }
#pragma unroll
            for (int qp = 0; qp < 2; qp++) {
                ulonglong2 w01 = __ldg(&WV2[qp * 32 + i4 * 2]);
                ulonglong2 w23 = __ldg(&WV2[qp * 32 + i4 * 2 + 1]);
                FFMA2(accV[qp][0], w01.x, da[0]); FFMA2(accV[qp][0], w01.y, da[1]);
                FFMA2(accV[qp][0], w23.x, da[2]); FFMA2(accV[qp][0], w23.y, da[3]);
                FFMA2(accV[qp][1], w01.x, db[0]); FFMA2(accV[qp][1], w01.y, db[1]);
                FFMA2(accV[qp][1], w23.x, db[2]); FFMA2(accV[qp][1], w23.y, db[3]);
            }
        }
        // K stores (float4, conflict-free)
        {
            int oc0 = pp0 * 2;
            int ob0 = oK + (st * 49 + lane) * 68 + oc0;
            int ob1 = oK + (st * 49 + lane + 32) * 68 + oc0;
#pragma unroll
            for (int g = 0; g < 2; g++) {
                float q0, q1, q2, q3;
                UNPACK2(q0, q1, accK[2 * g][0]); UNPACK2(q2, q3, accK[2 * g + 1][0]);
                *reinterpret_cast<float4*>(&sm[ob0 + g * 4]) = make_float4(q0, q1, q2, q3);
                if (has1) {
                    UNPACK2(q0, q1, accK[2 * g][1]); UNPACK2(q2, q3, accK[2 * g + 1][1]);
                    *reinterpret_cast<float4*>(&sm[ob1 + g * 4]) = make_float4(q0, q1, q2, q3);
                }
            }
        }
        // V stores (float4)
        {
            int oc0 = vp0 * 2;
            int ob0 = oV + (st * 49 + lane) * 36 + oc0;
            int ob1 = oV + (st * 49 + lane + 32) * 36 + oc0;
            float q0, q1, q2, q3;
            UNPACK2(q0, q1, accV[0][0]); UNPACK2(q2, q3, accV[1][0]);
            *reinterpret_cast<float4*>(&sm[ob0]) = make_float4(q0, q1, q2, q3);
            if (has1) {
                UNPACK2(q0, q1, accV[0][1]); UNPACK2(q2, q3, accV[1][1]);
                *reinterpret_cast<float4*>(&sm[ob1]) = make_float4(q0, q1, q2, q3);
            }
        }
    }
    __syncthreads();

    // ---- Phase 3: E = exp(scale * k1 . k2) + transposed copy ET ----
    // Balanced: each warp owns one contiguous 6-7 row slice of one head.
    const float SCALE = 0.17677669529663687f;   // 1/sqrt(32)
    {
        int n  = wid >> 3;
        int w8 = wid & 7;
        int x0 = w8 ? (1 + w8 * 6) : 0;          // 0,7,13,19,25,31,37,43
        int R  = w8 ? 6 : 7;
        float acc[7][2];
#pragma unroll
        for (int xx = 0; xx < 7; xx++) { acc[xx][0] = 0.f; acc[xx][1] = 0.f; }
        const float4* k2a = reinterpret_cast<const float4*>(&sm[oK + (49 + lane) * 68 + n * 32]);
        const float4* k2b = reinterpret_cast<const float4*>(&sm[oK + (49 + lane + 32) * 68 + n * 32]);
#pragma unroll
        for (int c4 = 0; c4 < 8; c4++) {
            float4 e0 = k2a[c4];
            float4 e1 = has1 ? k2b[c4] : make_float4(0.f, 0.f, 0.f, 0.f);
#pragma unroll
            for (int xx = 0; xx < 7; xx++) {
                if (xx < R) {
                    float4 k1 = *reinterpret_cast<const float4*>(
                        &sm[oK + (x0 + xx) * 68 + n * 32 + c4 * 4]);     // broadcast
                    acc[xx][0] += k1.x * e0.x + k1.y * e0.y + k1.z * e0.z + k1.w * e0.w;
                    acc[xx][1] += k1.x * e1.x + k1.y * e1.y + k1.z * e1.z + k1.w * e1.w;
                }
            }
        }
#pragma unroll
        for (int xx = 0; xx < 7; xx++) {
            if (xx < R) {
                int x = x0 + xx;
                float v0 = __expf(acc[xx][0] * SCALE);
                sm[oE + (n * 49 + x) * 52 + lane] = v0;
                sm[oET + (n * 49 + lane) * 52 + x] = v0;
                if (has1) {
                    float v1 = __expf(acc[xx][1] * SCALE);
                    sm[oE + (n * 49 + x) * 52 + lane + 32] = v1;
                    sm[oET + (n * 49 + lane + 32) * 52 + x] = v1;
                }
            }
        }
    }
    __syncthreads();

    // ---- Phase 4: reciprocal column / row sums (12 float4 + scalar tail) ----
    for (int idx = tid; idx < 196; idx += BDIM) {
        int half = idx / 98;
        int r = idx % 98;
        int rb = (half ? oE : oET) + r * 52;
        const float4* row = reinterpret_cast<const float4*>(&sm[rb]);
        float ssum = sm[rb + 48];
#pragma unroll
        for (int j4 = 0; j4 < 12; j4++) {
            float4 e = row[j4];
            ssum += e.x + e.y + e.z + e.w;
        }
        sm[(half ? oRS : oCS) + r] = 1.f / ssum;
    }
    __syncthreads();

    // ---- Phase 5: o1 / o2 -> OT[p][i]; 16 warp-tasks; 12 vec iters + tail ----
    {
        int which = wid >> 3;
        int n  = (wid >> 2) & 1;
        int dg = wid & 3;
        u64 acc[2][2] = {{0ull, 0ull}, {0ull, 0ull}};
        int erow0 = (which ? oE : oET) + (n * 49 + lane) * 52;
        int erow1 = (which ? oE : oET) + (n * 49 + lane + 32) * 52;
        int vbase = oV + which * 49 * 36 + n * 16 + dg * 4;
#pragma unroll
        for (int k4 = 0; k4 < 12; k4++) {
            float4 e0 = *reinterpret_cast<const float4*>(&sm[erow0 + k4 * 4]);
            float4 e1 = has1 ? *reinterpret_cast<const float4*>(&sm[erow1 + k4 * 4])
                             : make_float4(0.f, 0.f, 0.f, 0.f);
            float ea[4] = {e0.x, e0.y, e0.z, e0.w};
            float eb[4] = {e1.x, e1.y, e1.z, e1.w};
#pragma unroll
            for (int k = 0; k < 4; k++) {
                ulonglong2 v2 = *reinterpret_cast<const ulonglong2*>(&sm[vbase + (k4 * 4 + k) * 36]);
                u64 d0, d1;
                DUP2(d0, ea[k]); DUP2(d1, eb[k]);
                FFMA2(acc[0][0], v2.x, d0); FFMA2(acc[1][0], v2.y, d0);
                FFMA2(acc[0][1], v2.x, d1); FFMA2(acc[1][1], v2.y, d1);
            }
        }
        {   // tail k = 48
            float e0 = sm[erow0 + 48];
            float e1 = has1 ? sm[erow1 + 48] : 0.f;
            ulonglong2 v2 = *reinterpret_cast<const ulonglong2*>(&sm[vbase + 48 * 36]);
            u64 d0, d1;
            DUP2(d0, e0); DUP2(d1, e1);
            FFMA2(acc[0][0], v2.x, d0); FFMA2(acc[1][0], v2.y, d0);
            FFMA2(acc[0][1], v2.x, d1); FFMA2(acc[1][1], v2.y, d1);
        }
        int fbase = (which ? oRS : oCS) + n * 49;
        float f0 = sm[fbase + lane];
        float f1 = has1 ? sm[fbase + lane + 32] : 0.f;
        int col = which * 32 + n * 16 + dg * 4;
        float a0, a1, a2, a3;
        UNPACK2(a0, a1, acc[0][0]); UNPACK2(a2, a3, acc[1][0]);
        *reinterpret_cast<float4*>(&sm[oOT + lane * 68 + col]) =
            make_float4(a0 * f0, a1 * f0, a2 * f0, a3 * f0);
        if (has1) {
            UNPACK2(a0, a1, acc[0][1]); UNPACK2(a2, a3, acc[1][1]);
            *reinterpret_cast<float4*>(&sm[oOT + (lane + 32) * 68 + col]) =
                make_float4(a0 * f1, a1 * f1, a2 * f1, a3 * f1);
        }
    }
    __syncthreads();

    // ---- Phase 6: Out[c][p] = bp[c] + sum_i OT[p][i] * Wp[c][i] ----
    {
        int c0 = wid * 4;
        int cp0 = wid * 2;
        u64 acc[2][2];
#pragma unroll
        for (int j = 0; j < 2; j++) {
            u64 bb; PACK2(bb, __ldg(&bp[c0 + 2 * j]), __ldg(&bp[c0 + 2 * j + 1]));
            acc[j][0] = bb; acc[j][1] = bb;
        }
        const ulonglong2* W2 = reinterpret_cast<const ulonglong2*>(&gWp2[cp0 * 64]);
#pragma unroll
        for (int i4 = 0; i4 < 16; i4++) {
            float4 oa = *reinterpret_cast<const float4*>(&sm[oOT + lane * 68 + i4 * 4]);
            float4 ob = has1 ? *reinterpret_cast<const float4*>(&sm[oOT + (lane + 32) * 68 + i4 * 4])
                             : make_float4(0.f, 0.f, 0.f, 0.f);
            u64 da[4], db[4];
            DUP2(da[0], oa.x); DUP2(da[1], oa.y); DUP2(da[2], oa.z); DUP2(da[3], oa.w);
            DUP2(db[0], ob.x); DUP2(db[1], ob.y); DUP2(db[2], ob.z); DUP2(db[3], ob.w);
#pragma unroll
            for (int j = 0; j < 2; j++) {
                ulonglong2 w01 = __ldg(&W2[j * 32 + i4 * 2]);
                ulonglong2 w23 = __ldg(&W2[j * 32 + i4 * 2 + 1]);
                FFMA2(acc[j][0], w01.x, da[0]); FFMA2(acc[j][0], w01.y, da[1]);
                FFMA2(acc[j][0], w23.x, da[2]); FFMA2(acc[j][0], w23.y, da[3]);
                FFMA2(acc[j][1], w01.x, db[0]); FFMA2(acc[j][1], w01.y, db[1]);
                FFMA2(acc[j][1], w23.x, db[2]); FFMA2(acc[j][1], w23.y, db[3]);
            }
        }
        float q0, q1, q2, q3;
        UNPACK2(q0, q1, acc[0][0]); UNPACK2(q2, q3, acc[1][0]);
        sm[oOut + (c0 + 0) * 49 + lane] = q0;
        sm[oOut + (c0 + 1) * 49 + lane] = q1;
        sm[oOut + (c0 + 2) * 49 + lane] = q2;
        sm[oOut + (c0 + 3) * 49 + lane] = q3;
        if (has1) {
            UNPACK2(q0, q1, acc[0][1]); UNPACK2(q2, q3, acc[1][1]);
            sm[oOut + (c0 + 0) * 49 + lane + 32] = q0;
            sm[oOut + (c0 + 1) * 49 + lane + 32] = q1;
            sm[oOut + (c0 + 2) * 49 + lane + 32] = q2;
            sm[oOut + (c0 + 3) * 49 + lane + 32] = q3;
        }
    }
    __syncthreads();

    // ---- Phase 7: scatter stores ----
    for (int idx = tid; idx < 64 * 49; idx += BDIM) {
        int c = idx / 49;
        int p = idx % 49;
        int px = p / 7, py = p % 7;
        int h = si * 21 + px * 4, w = sj * 21 + py * 4;
        out[((b * 64 + c) * 256 + h) * 256 + w] = sm[oOut + idx];
    }
}

extern "C" void kernel_launch(void* const* d_in, const int* in_sizes, int n_in,
                              void* d_out, int out_size) {
    const float* x1 = (const float*)d_in[0];
    const float* x2 = (const float*)d_in[1];
    const float* Wk = (const float*)d_in[2];
    const float* bk = (const float*)d_in[3];
    const float* Wv = (const float*)d_in[4];
    const float* bv = (const float*)d_in[5];
    const float* Wp = (const float*)d_in[6];
    const float* bp = (const float*)d_in[7];
    float* out = (float*)d_out;

    repack_kernel<<<32, 256>>>(Wk, Wv, Wp);

    cudaFuncSetAttribute(fused_kernel,
                         cudaFuncAttributeMaxDynamicSharedMemorySize, SMEM_BYTES);
    fused_kernel<<<N_ATTN + N_FILL, BDIM, SMEM_BYTES>>>(x1, x2, Wk, bk, Wv, bv, Wp, bp, out);
}

// round 10
// speedup vs baseline: 6.0002x; 1.0620x over previous
#include <cuda_runtime.h>

// ---------------------------------------------------------------------------
// B=8, H=W=256, I_DIM=64, K_DIM=64/stream, V_DIM=32/stream, NH=2 (hd_k=32, hd_v=16)
// unfold(256, P=7, NK=4) -> p=7, stride=21, dilation=4, nk=12
// => 144 patches of 49 px; positions {21i+4j} all distinct per dim
// => fold has no overlap; attn writes exactly Sh x Sw, fill writes the rest.
// f32x2 packed fp32 FMA; packed weights via __ldg (L1-resident broadcasts).
// R10: P4 folded into P5 (sums computed in-flight), P7 folded into P6
// (direct gmem scatter) -> 4 barriers instead of 6.
// ---------------------------------------------------------------------------

#define BDIM 512           // 16 warps
#define N_ATTN 1152        // 8 batches * 144 patches
#define N_FILL 2048        // fill blocks (8 float4 per thread)

typedef unsigned long long u64;

#define FFMA2(acc, a, b) asm("fma.rn.f32x2 %0, %1, %2, %0;" : "+l"(acc) : "l"(a), "l"(b))
#define DUP2(d, v)       asm("mov.b64 %0, {%1, %1};"        : "=l"(d)   : "f"(v))
#define PACK2(d, lo, hi) asm("mov.b64 %0, {%1, %2};"        : "=l"(d)   : "f"(lo), "f"(hi))
#define UNPACK2(lo, hi, d) asm("mov.b64 {%0, %1}, %2;"      : "=f"(lo), "=f"(hi) : "l"(d))

// Packed weight-pair buffers (lo = even output channel, hi = odd).
__device__ __align__(16) u64 gWk2[2 * 32 * 64];   // (st*32 + qp)*64 + c
__device__ __align__(16) u64 gWv2[2 * 16 * 64];   // (st*16 + qp)*64 + c
__device__ __align__(16) u64 gWp2[32 * 64];       // cp*64 + i

__global__ void repack_kernel(const float* __restrict__ Wk, const float* __restrict__ Wv,
                              const float* __restrict__ Wp) {
    int t = blockIdx.x * blockDim.x + threadIdx.x;
    int nt = gridDim.x * blockDim.x;
    for (int i = t; i < 4096; i += nt) {            // Wk pairs
        int c = i & 63, qp = (i >> 6) & 31, st = i >> 11;
        u64 d; PACK2(d, Wk[(st * 64 + 2 * qp) * 64 + c], Wk[(st * 64 + 2 * qp + 1) * 64 + c]);
        gWk2[i] = d;
    }
    for (int i = t; i < 2048; i += nt) {            // Wv pairs
        int c = i & 63, qp = (i >> 6) & 15, st = i >> 10;
        u64 d; PACK2(d, Wv[(st * 32 + 2 * qp) * 64 + c], Wv[(st * 32 + 2 * qp + 1) * 64 + c]);
        gWv2[i] = d;
    }
    for (int i = t; i < 2048; i += nt) {            // Wp pairs
        int ic = i & 63, cp = i >> 6;
        u64 d; PACK2(d, Wp[(2 * cp) * 64 + ic], Wp[(2 * cp + 1) * 64 + ic]);
        gWp2[i] = d;
    }
}

// ---- smem layout (float offsets) ----
constexpr int oX   = 0;
constexpr int oE   = 0;                  // E[(n*49+x)*52 + y]
constexpr int oET  = 5096;               // ET[(n*49+y)*52 + x]
constexpr int oA_SZ = 10192;
constexpr int oK   = oA_SZ;              // K[(st*49+p)*68 + c]
constexpr int oOT  = oA_SZ;              // OT[p*68 + i]
constexpr int oV   = oA_SZ + 6664;       // V[(st*49+p)*36 + d]  (98 rows)
constexpr int SMEMF = oV + 98 * 36;
constexpr int SMEM_BYTES = SMEMF * 4;    // 81536 bytes -> 2 CTAs/SM

// v in [0,256) is sampled iff v = 21*i + 4*j, i<12, j<7. 21 ≡ 1 (mod 4).
__device__ __forceinline__ bool is_sampled(int v) {
    int i = v & 3;
#pragma unroll
    for (int t = 0; t < 3; t++, i += 4) {
        int d = v - 21 * i;
        if (i < 12 && d >= 0 && d <= 24) return true;
    }
    return false;
}

__global__ void __launch_bounds__(BDIM, 2)
fused_kernel(const float* __restrict__ x1, const float* __restrict__ x2,
             const float* __restrict__ Wk, const float* __restrict__ bk,
             const float* __restrict__ Wv, const float* __restrict__ bv,
             const float* __restrict__ Wp, const float* __restrict__ bp,
             float* __restrict__ out) {
    // ======================= FILL PATH ===================
    if (blockIdx.x >= N_ATTN) {
        unsigned g = (blockIdx.x - N_ATTN) * BDIM + threadIdx.x;
#pragma unroll
        for (int k = 0; k < 8; k++) {
            unsigned i = g + k * (N_FILL * BDIM);
            int w4 = (i & 63) << 2;
            int h  = (i >> 6) & 255;
            int c  = (i >> 14) & 63;
            float v = __ldg(&bp[c]);
            if (!is_sampled(h)) {
                reinterpret_cast<float4*>(out)[i] = make_float4(v, v, v, v);
            } else {
                float* o = out + (size_t)i * 4;
#pragma unroll
                for (int q = 0; q < 4; q++)
                    if (!is_sampled(w4 + q)) o[q] = v;
            }
        }
        return;
    }

    // ======================= ATTENTION PATH =================================
    extern __shared__ __align__(16) float sm[];
    const int tid  = threadIdx.x;
    const int lane = tid & 31;
    const int wid  = tid >> 5;
    const bool has1 = (lane < 17);

    const int b  = blockIdx.x / 144;
    const int s  = blockIdx.x % 144;
    const int si = s / 12, sj = s % 12;

    // ---- Phase 1: gather x1/x2 at the 49 patch pixels ----
    for (int idx = tid; idx < 2 * 64 * 49; idx += BDIM) {
        int st = idx / 3136;
        int r  = idx % 3136;
        int c  = r / 49;
        int p  = r % 49;
        int px = p / 7, py = p % 7;
        int h = si * 21 + px * 4, w = sj * 21 + py * 4;
        const float* xp = st ? x2 : x1;
        sm[oX + (st * 49 + p) * 68 + c] = __ldg(&xp[((b * 64 + c) * 256 + h) * 256 + w]);
    }
    __syncthreads();

    // ---- Phase 2: fused K+V 1x1 convs; X loaded once, DUPs shared ----
    {
        const int st  = wid >> 3;
        const int sub = wid & 7;
        const int pp0 = sub * 4;            // 4 K oc-pairs
        const int vp0 = sub * 2;            // 2 V oc-pairs
        const ulonglong2* WK2 = reinterpret_cast<const ulonglong2*>(&gWk2[(st * 32 + pp0) * 64]);
        const ulonglong2* WV2 = reinterpret_cast<const ulonglong2*>(&gWv2[(st * 16 + vp0) * 64]);
        u64 accK[4][2], accV[2][2];
#pragma unroll
        for (int qp = 0; qp < 4; qp++) {
            u64 bb; PACK2(bb, __ldg(&bk[st * 64 + 2 * (pp0 + qp)]),
                              __ldg(&bk[st * 64 + 2 * (pp0 + qp) + 1]));
            accK[qp][0] = bb; accK[qp][1] = bb;
        }
#pragma unroll
        for (int qp = 0; qp < 2; qp++) {
            u64 bb; PACK2(bb, __ldg(&bv[st * 32 + 2 * (vp0 + qp)]),
                              __ldg(&bv[st * 32 + 2 * (vp0 + qp) + 1]));
            accV[qp][0] = bb; accV[qp][1] = bb;
        }
        const float4* xa = reinterpret_cast<const float4*>(&sm[oX + (st * 49 + lane) * 68]);
        const float4* xb = reinterpret_cast<const float4*>(&sm[oX + (st * 49 + lane + 32) * 68]);
#pragma unroll
        for (int i4 = 0; i4 < 16; i4++) {
            float4 a = xa[i4];
            float4 bx = has1 ? xb[i4] : make_float4(0.f, 0.f, 0.f, 0.f);
            u64 da[4], db[4];
            DUP2(da[0], a.x); DUP2(da[1], a.y); DUP2(da[2], a.z); DUP2(da[3], a.w);
            DUP2(db[0], bx.x); DUP2(db[1], bx.y); DUP2(db[2], bx.z); DUP2(db[3], bx.w);
#pragma unroll
            for (int qp = 0; qp < 4; qp++) {
                ulonglong2 w01 = __ldg(&WK2[qp * 32 + i4 * 2]);
                ulonglong2 w23 = __ldg(&WK2[qp * 32 + i4 * 2 + 1]);
                FFMA2(accK[qp][0], w01.x, da[0]); FFMA2(accK[qp][0], w01.y, da[1]);
                FFMA2(accK[qp][0], w23.x, da[2]); FFMA2(accK[qp][0], w23.y, da[3]);
                FFMA2(accK[qp][1], w01.x, db[0]); FFMA2(accK[qp][1], w01.y, db[1]);
                FFMA2(accK[qp][1], w23.x, db[2]); FFMA2(accK[qp][1], w23.y, db[3]);
            }
#pragma unroll
            for (int qp = 0; qp < 2; qp++) {
                ulonglong2 w01 = __ldg(&WV2[qp * 32 + i4 * 2]);
                ulonglong2 w23 = __ldg(&WV2[qp * 32 + i4 * 2 + 1]);
                FFMA2(accV[qp][0], w01.x, da[0]); FFMA2(accV[qp][0], w01.y, da[1]);
                FFMA2(accV[qp][0], w23.x, da[2]); FFMA2(accV[qp][0], w23.y, da[3]);
                FFMA2(accV[qp][1], w01.x, db[0]); FFMA2(accV[qp][1], w01.y, db[1]);
                FFMA2(accV[qp][1], w23.x, db[2]); FFMA2(accV[qp][1], w23.y, db[3]);
            }
        }
        // K stores (float4, conflict-free)
        {
            int oc0 = pp0 * 2;
            int ob0 = oK + (st * 49 + lane) * 68 + oc0;
            int ob1 = oK + (st * 49 + lane + 32) * 68 + oc0;
#pragma unroll
            for (int g = 0; g < 2; g++) {
                float q0, q1, q2, q3;
                UNPACK2(q0, q1, accK[2 * g][0]); UNPACK2(q2, q3, accK[2 * g + 1][0]);
                *reinterpret_cast<float4*>(&sm[ob0 + g * 4]) = make_float4(q0, q1, q2, q3);
                if (has1) {
                    UNPACK2(q0, q1, accK[2 * g][1]); UNPACK2(q2, q3, accK[2 * g + 1][1]);
                    *reinterpret_cast<float4*>(&sm[ob1 + g * 4]) = make_float4(q0, q1, q2, q3);
                }
            }
        }
        // V stores (float4)
        {
            int oc0 = vp0 * 2;
            int ob0 = oV + (st * 49 + lane) * 36 + oc0;
            int ob1 = oV + (st * 49 + lane + 32) * 36 + oc0;
            float q0, q1, q2, q3;
            UNPACK2(q0, q1, accV[0][0]); UNPACK2(q2, q3, accV[1][0]);
            *reinterpret_cast<float4*>(&sm[ob0]) = make_float4(q0, q1, q2, q3);
            if (has1) {
                UNPACK2(q0, q1, accV[0][1]); UNPACK2(q2, q3, accV[1][1]);
                *reinterpret_cast<float4*>(&sm[ob1]) = make_float4(q0, q1, q2, q3);
            }
        }
    }
    __syncthreads();

    // ---- Phase 3: E = exp(scale * k1 . k2) + transposed copy ET ----
    // Balanced: each warp owns one contiguous 6-7 row slice of one head.
    const float SCALE = 0.17677669529663687f;   // 1/sqrt(32)
    {
        int n  = wid >> 3;
        int w8 = wid & 7;
        int x0 = w8 ? (1 + w8 * 6) : 0;          // 0,7,13,19,25,31,37,43
        int R  = w8 ? 6 : 7;
        float acc[7][2];
#pragma unroll
        for (int xx = 0; xx < 7; xx++) { acc[xx][0] = 0.f; acc[xx][1] = 0.f; }
        const float4* k2a = reinterpret_cast<const float4*>(&sm[oK + (49 + lane) * 68 + n * 32]);
        const float4* k2b = reinterpret_cast<const float4*>(&sm[oK + (49 + lane + 32) * 68 + n * 32]);
#pragma unroll
        for (int c4 = 0; c4 < 8; c4++) {
            float4 e0 = k2a[c4];
            float4 e1 = has1 ? k2b[c4] : make_float4(0.f, 0.f, 0.f, 0.f);
#pragma unroll
            for (int xx = 0; xx < 7; xx++) {
                if (xx < R) {
                    float4 k1 = *reinterpret_cast<const float4*>(
                        &sm[oK + (x0 + xx) * 68 + n * 32 + c4 * 4]);     // broadcast
                    acc[xx][0] += k1.x * e0.x + k1.y * e0.y + k1.z * e0.z + k1.w * e0.w;
                    acc[xx][1] += k1.x * e1.x + k1.y * e1.y + k1.z * e1.z + k1.w * e1.w;
                }
            }
        }
#pragma unroll
        for (int xx = 0; xx < 7; xx++) {
            if (xx < R) {
                int x = x0 + xx;
                float v0 = __expf(acc[xx][0] * SCALE);
                sm[oE + (n * 49 + x) * 52 + lane] = v0;
                sm[oET + (n * 49 + lane) * 52 + x] = v0;
                if (has1) {
                    float v1 = __expf(acc[xx][1] * SCALE);
                    sm[oE + (n * 49 + x) * 52 + lane + 32] = v1;
                    sm[oET + (n * 49 + lane + 32) * 52 + x] = v1;
                }
            }
        }
    }
    __syncthreads();

    // ---- Phase 5: o1 / o2 -> OT[p][i]; sums folded in (ex-P4); 16 warp-tasks ----
    {
        int which = wid >> 3;
        int n  = (wid >> 2) & 1;
        int dg = wid & 3;
        u64 acc[2][2] = {{0ull, 0ull}, {0ull, 0ull}};
        float ssum0 = 0.f, ssum1 = 0.f;          // row sums of the E/ET rows we read
        int erow0 = (which ? oE : oET) + (n * 49 + lane) * 52;
        int erow1 = (which ? oE : oET) + (n * 49 + lane + 32) * 52;
        int vbase = oV + which * 49 * 36 + n * 16 + dg * 4;
#pragma unroll
        for (int k4 = 0; k4 < 12; k4++) {
            float4 e0 = *reinterpret_cast<const float4*>(&sm[erow0 + k4 * 4]);
            float4 e1 = has1 ? *reinterpret_cast<const float4*>(&sm[erow1 + k4 * 4])
                             : make_float4(0.f, 0.f, 0.f, 0.f);
            ssum0 += e0.x + e0.y + e0.z + e0.w;
            ssum1 += e1.x + e1.y + e1.z + e1.w;
            float ea[4] = {e0.x, e0.y, e0.z, e0.w};
            float eb[4] = {e1.x, e1.y, e1.z, e1.w};
#pragma unroll
            for (int k = 0; k < 4; k++) {
                ulonglong2 v2 = *reinterpret_cast<const ulonglong2*>(&sm[vbase + (k4 * 4 + k) * 36]);
                u64 d0, d1;
                DUP2(d0, ea[k]); DUP2(d1, eb[k]);
                FFMA2(acc[0][0], v2.x, d0); FFMA2(acc[1][0], v2.y, d0);
                FFMA2(acc[0][1], v2.x, d1); FFMA2(acc[1][1], v2.y, d1);
            }
        }
        {   // tail k = 48
            float e0 = sm[erow0 + 48];
            float e1 = has1 ? sm[erow1 + 48] : 0.f;
            ssum0 += e0; ssum1 += e1;
            ulonglong2 v2 = *reinterpret_cast<const ulonglong2*>(&sm[vbase + 48 * 36]);
            u64 d0, d1;
            DUP2(d0, e0); DUP2(d1, e1);
            FFMA2(acc[0][0], v2.x, d0); FFMA2(acc[1][0], v2.y, d0);
            FFMA2(acc[0][1], v2.x, d1); FFMA2(acc[1][1], v2.y, d1);
        }
        float f0 = 1.f / ssum0;
        float f1 = has1 ? (1.f / ssum1) : 0.f;
        int col = which * 32 + n * 16 + dg * 4;
        float a0, a1, a2, a3;
        UNPACK2(a0, a1, acc[0][0]); UNPACK2(a2, a3, acc[1][0]);
        *reinterpret_cast<float4*>(&sm[oOT + lane * 68 + col]) =
            make_float4(a0 * f0, a1 * f0, a2 * f0, a3 * f0);
        if (has1) {
            UNPACK2(a0, a1, acc[0][1]); UNPACK2(a2, a3, acc[1][1]);
            *reinterpret_cast<float4*>(&sm[oOT + (lane + 32) * 68 + col]) =
                make_float4(a0 * f1, a1 * f1, a2 * f1, a3 * f1);
        }
    }
    __syncthreads();

    // ---- Phase 6: Out[c][p] = bp[c] + sum_i OT[p][i]*Wp[c][i]; direct gmem scatter ----
    {
        int c0 = wid * 4;
        int cp0 = wid * 2;
        u64 acc[2][2];
#pragma unroll
        for (int j = 0; j < 2; j++) {
            u64 bb; PACK2(bb, __ldg(&bp[c0 + 2 * j]), __ldg(&bp[c0 + 2 * j + 1]));
            acc[j][0] = bb; acc[j][1] = bb;
        }
        const ulonglong2* W2 = reinterpret_cast<const ulonglong2*>(&gWp2[cp0 * 64]);
#pragma unroll
        for (int i4 = 0; i4 < 16; i4++) {
            float4 oa = *reinterpret_cast<const float4*>(&sm[oOT + lane * 68 + i4 * 4]);
            float4 ob = has1 ? *reinterpret_cast<const float4*>(&sm[oOT + (lane + 32) * 68 + i4 * 4])
                             : make_float4(0.f, 0.f, 0.f, 0.f);
            u64 da[4], db[4];
            DUP2(da[0], oa.x); DUP2(da[1], oa.y); DUP2(da[2], oa.z); DUP2(da[3], oa.w);
            DUP2(db[0], ob.x); DUP2(db[1], ob.y); DUP2(db[2], ob.z); DUP2(db[3], ob.w);
#pragma unroll
            for (int j = 0; j < 2; j++) {
                ulonglong2 w01 = __ldg(&W2[j * 32 + i4 * 2]);
                ulonglong2 w23 = __ldg(&W2[j * 32 + i4 * 2 + 1]);
                FFMA2(acc[j][0], w01.x, da[0]); FFMA2(acc[j][0], w01.y, da[1]);
                FFMA2(acc[j][0], w23.x, da[2]); FFMA2(acc[j][0], w23.y, da[3]);
                FFMA2(acc[j][1], w01.x, db[0]); FFMA2(acc[j][1], w01.y, db[1]);
                FFMA2(acc[j][1], w23.x, db[2]); FFMA2(acc[j][1], w23.y, db[3]);
            }
        }
        // direct scatter: p0 = lane, p1 = lane + 32
        {
            int p0 = lane;
            int h0 = si * 21 + (p0 / 7) * 4, w0 = sj * 21 + (p0 % 7) * 4;
            float* o0 = out + ((size_t)(b * 64 + c0) * 256 + h0) * 256 + w0;
            float q0, q1, q2, q3;
            UNPACK2(q0, q1, acc[0][0]); UNPACK2(q2, q3, acc[1][0]);
            o0[0 * 65536] = q0; o0[1 * 65536] = q1; o0[2 * 65536] = q2; o0[3 * 65536] = q3;
            if (has1) {
                int p1 = lane + 32;
                int h1 = si * 21 + (p1 / 7) * 4, w1 = sj * 21 + (p1 % 7) * 4;
                float* o1 = out + ((size_t)(b * 64 + c0) * 256 + h1) * 256 + w1;
                UNPACK2(q0, q1, acc[0][1]); UNPACK2(q2, q3, acc[1][1]);
                o1[0 * 65536] = q0; o1[1 * 65536] = q1; o1[2 * 65536] = q2; o1[3 * 65536] = q3;
            }
        }
    }
}

extern "C" void kernel_launch(void* const* d_in, const int* in_sizes, int n_in,
                              void* d_out, int out_size) {
    const float* x1 = (const float*)d_in[0];
    const float* x2 = (const float*)d_in[1];
    const float* Wk = (const float*)d_in[2];
    const float* bk = (const float*)d_in[3];
    const float* Wv = (const float*)d_in[4];
    const float* bv = (const float*)d_in[5];
    const float* Wp = (const float*)d_in[6];
    const float* bp = (const float*)d_in[7];
    float* out = (float*)d_out;

    repack_kernel<<<32, 256>>>(Wk, Wv, Wp);

    cudaFuncSetAttribute(fused_kernel,
                         cudaFuncAttributeMaxDynamicSharedMemorySize, SMEM_BYTES);
    fused_kernel<<<N_ATTN + N_FILL, BDIM, SMEM_BYTES>>>(x1, x2, Wk, bk, Wv, bv, Wp, bp, out);
}

// round 11
// speedup vs baseline: 6.4926x; 1.0821x over previous
#include <cuda_runtime.h>

// ---------------------------------------------------------------------------
// B=8, H=W=256, I_DIM=64, K_DIM=64/stream, V_DIM=32/stream, NH=2 (hd_k=32, hd_v=16)
// unfold(256, P=7, NK=4) -> p=7, stride=21, dilation=4, nk=12
// => 144 patches of 49 px; positions {21i+4j} all distinct per dim
// => fold has no overlap; attn writes exactly Sh x Sw, fill writes the rest.
// f32x2 packed fp32 FMA; packed weights via __ldg; x gather via __ldcg (L2-only,
// zero-reuse data, keeps weights L1-resident). Fill uses precomputed 256-bit
// sampled-mask constants + warp-per-row layout.
// ---------------------------------------------------------------------------

#define BDIM 512           // 16 warps
#define N_ATTN 1152        // 8 batches * 144 patches
#define N_FILL 2048        // fill blocks: 16 warps x 4 rows = 64 rows/block

typedef unsigned long long u64;

#define FFMA2(acc, a, b) asm("fma.rn.f32x2 %0, %1, %2, %0;" : "+l"(acc) : "l"(a), "l"(b))
#define DUP2(d, v)       asm("mov.b64 %0, {%1, %1};"        : "=l"(d)   : "f"(v))
#define PACK2(d, lo, hi) asm("mov.b64 %0, {%1, %2};"        : "=l"(d)   : "f"(lo), "f"(hi))
#define UNPACK2(lo, hi, d) asm("mov.b64 {%0, %1}, %2;"      : "=f"(lo), "=f"(hi) : "l"(d))

// 256-bit sampled mask: bit v set iff v = 21*i + 4*j (i<12, j<7).
// Precomputed: word0 = bits 0-63, ..., word3 = bits 192-255.
__device__ __forceinline__ u64 mask_word(int idx) {
    u64 w01 = (idx & 1) ? 0x622233111198888CULL : 0xC444662223311111ULL;
    u64 w23 = (idx & 1) ? 0x88888CC444662223ULL : 0x3111198888CC4446ULL;
    return (idx & 2) ? w23 : w01;
}

// Packed weight-pair buffers (lo = even output channel, hi = odd).
__device__ __align__(16) u64 gWk2[2 * 32 * 64];   // (st*32 + qp)*64 + c
__device__ __align__(16) u64 gWv2[2 * 16 * 64];   // (st*16 + qp)*64 + c
__device__ __align__(16) u64 gWp2[32 * 64];       // cp*64 + i

__global__ void repack_kernel(const float* __restrict__ Wk, const float* __restrict__ Wv,
                              const float* __restrict__ Wp) {
    int t = blockIdx.x * blockDim.x + threadIdx.x;
    int nt = gridDim.x * blockDim.x;
    for (int i = t; i < 4096; i += nt) {            // Wk pairs
        int c = i & 63, qp = (i >> 6) & 31, st = i >> 11;
        u64 d; PACK2(d, Wk[(st * 64 + 2 * qp) * 64 + c], Wk[(st * 64 + 2 * qp + 1) * 64 + c]);
        gWk2[i] = d;
    }
    for (int i = t; i < 2048; i += nt) {            // Wv pairs
        int c = i & 63, qp = (i >> 6) & 15, st = i >> 10;
        u64 d; PACK2(d, Wv[(st * 32 + 2 * qp) * 64 + c], Wv[(st * 32 + 2 * qp + 1) * 64 + c]);
        gWv2[i] = d;
    }
    for (int i = t; i < 2048; i += nt) {            // Wp pairs
        int ic = i & 63, cp = i >> 6;
        u64 d; PACK2(d, Wp[(2 * cp) * 64 + ic], Wp[(2 * cp + 1) * 64 + ic]);
        gWp2[i] = d;
    }
}

// ---- smem layout (float offsets) ----
constexpr int oX   = 0;
constexpr int oE   = 0;                  // E[(n*49+x)*52 + y]
constexpr int oET  = 5096;               // ET[(n*49+y)*52 + x]
constexpr int oA_SZ = 10192;
constexpr int oK   = oA_SZ;              // K[(st*49+p)*68 + c]
constexpr int oOT  = oA_SZ;              // OT[p*68 + i]
constexpr int oV   = oA_SZ + 6664;       // V[(st*49+p)*36 + d]  (98 rows)
constexpr int SMEMF = oV + 98 * 36;
constexpr int SMEM_BYTES = SMEMF * 4;    // 81536 bytes -> 2 CTAs/SM

__global__ void __launch_bounds__(BDIM, 2)
fused_kernel(const float* __restrict__ x1, const float* __restrict__ x2,
             const float* __restrict__ Wk, const float* __restrict__ bk,
             const float* __restrict__ Wv, const float* __restrict__ bv,
             const float* __restrict__ Wp, const float* __restrict__ bp,
             float* __restrict__ out) {
    const int tid  = threadIdx.x;
    const int lane = tid & 31;
    const int wid  = tid >> 5;

    // ======================= FILL PATH: warp-per-row ===================
    if (blockIdx.x >= N_ATTN) {
        int fb = blockIdx.x - N_ATTN;
        // per-lane float4-group sampling nibbles (loop-invariant)
        int g0 = lane, g1 = lane + 32;
        unsigned nib0 = (unsigned)((mask_word(g0 >> 4) >> ((g0 & 15) * 4)) & 0xF);
        unsigned nib1 = (unsigned)((mask_word(g1 >> 4) >> ((g1 & 15) * 4)) & 0xF);
        int rbase = (fb * 16 + wid) * 4;          // 4 rows per warp; 131072 total
#pragma unroll
        for (int k = 0; k < 4; k++) {
            int ri = rbase + k;                   // ri = (b*64 + c)*256 + h
            int h = ri & 255;
            int c = (ri >> 8) & 63;
            float v = __ldg(&bp[c]);
            float4 vv = make_float4(v, v, v, v);
            float* rowp = out + (size_t)ri * 256;
            bool hs = (mask_word(h >> 6) >> (h & 63)) & 1;
            if (!hs) {
                reinterpret_cast<float4*>(rowp)[g0] = vv;
                reinterpret_cast<float4*>(rowp)[g1] = vv;
            } else {
                if (nib0 == 0) {
                    reinterpret_cast<float4*>(rowp)[g0] = vv;
                } else {
#pragma unroll
                    for (int q = 0; q < 4; q++)
                        if (!((nib0 >> q) & 1)) rowp[g0 * 4 + q] = v;
                }
                if (nib1 == 0) {
                    reinterpret_cast<float4*>(rowp)[g1] = vv;
                } else {
#pragma unroll
                    for (int q = 0; q < 4; q++)
                        if (!((nib1 >> q) & 1)) rowp[g1 * 4 + q] = v;
                }
            }
        }
        return;
    }

    // ======================= ATTENTION PATH =================================
    extern __shared__ __align__(16) float sm[];
    const bool has1 = (lane < 17);

    const int b  = blockIdx.x / 144;
    const int s  = blockIdx.x % 144;
    const int si = s / 12, sj = s % 12;

    // ---- Phase 1: gather x1/x2; 4 channels per task, STS.128 (conflict-free) ----
    // 1568 tasks = 2 st * 16 cgroups * 49 p; x loads bypass L1 (__ldcg, zero reuse).
    for (int idx = tid; idx < 1568; idx += BDIM) {
        int stcg = idx / 49;
        int p = idx - stcg * 49;
        int st = stcg >> 4;
        int cg = stcg & 15;
        int px = p / 7, py = p % 7;
        int h = si * 21 + px * 4, w = sj * 21 + py * 4;
        const float* xp = (st ? x2 : x1) + ((size_t)(b * 64 + cg * 4) * 256 + h) * 256 + w;
        float4 val;
        val.x = __ldcg(xp);
        val.y = __ldcg(xp + 65536);
        val.z = __ldcg(xp + 131072);
        val.w = __ldcg(xp + 196608);
        *reinterpret_cast<float4*>(&sm[oX + (st * 49 + p) * 68 + cg * 4]) = val;
    }
    __syncthreads();

    // ---- Phase 2: fused K+V 1x1 convs; X loaded once, DUPs shared ----
    {
        const int st  = wid >> 3;
        const int sub = wid & 7;
        const int pp0 = sub * 4;            // 4 K oc-pairs
        const int vp0 = sub * 2;            // 2 V oc-pairs
        const ulonglong2* WK2 = reinterpret_cast<const ulonglong2*>(&gWk2[(st * 32 + pp0) * 64]);
        const ulonglong2* WV2 = reinterpret_cast<const ulonglong2*>(&gWv2[(st * 16 + vp0) * 64]);
        u64 accK[4][2], accV[2][2];
#pragma unroll
        for (int qp = 0; qp < 4; qp++) {
            u64 bb; PACK2(bb, __ldg(&bk[st * 64 + 2 * (pp0 + qp)]),
                              __ldg(&bk[st * 64 + 2 * (pp0 + qp) + 1]));
            accK[qp][0] = bb; accK[qp][1] = bb;
        }
#pragma unroll
        for (int qp = 0; qp < 2; qp++) {
            u64 bb; PACK2(bb, __ldg(&bv[st * 32 + 2 * (vp0 + qp)]),
                              __ldg(&bv[st * 32 + 2 * (vp0 + qp) + 1]));
            accV[qp][0] = bb; accV[qp][1] = bb;
        }
        const float4* xa = reinterpret_cast<const float4*>(&sm[oX + (st * 49 + lane) * 68]);
        const float4* xb = reinterpret_cast<const float4*>(&sm[oX + (st * 49 + lane + 32) * 68]);
#pragma unroll
        for (int i4 = 0; i4 < 16; i4++) {
            float4 a = xa[i4];
            float4 bx = has1 ? xb[i4] : make_float4(0.f, 0.f, 0.f, 0.f);
            u64 da[4], db[4];
            DUP2(da[0], a.x); DUP2(da[1], a.y); DUP2(da[2], a.z); DUP2(da[3], a.w);
            DUP2(db[0], bx.x); DUP2(db[1], bx.y); DUP2(db[2], bx.z); DUP2(db[3], bx.w);
#pragma unroll
            for (int qp = 0; qp < 4; qp++) {
                ulonglong2 w01 = __ldg(&WK2[qp * 32 + i4 * 2]);
                ulonglong2 w23 = __ldg(&WK2[qp * 32 + i4 * 2 + 1]);
                FFMA2(accK[qp][0], w01.x, da[0]); FFMA2(accK[qp][0], w01.y, da[1]);
                FFMA2(accK[qp][0], w23.x, da[2]); FFMA2(accK[qp][0], w23.y, da[3]);
                FFMA2(accK[qp][1], w01.x, db[0]); FFMA2(accK[qp][1], w01.y, db[1]);
                FFMA2(accK[qp][1], w23.x, db[2]); FFMA2(accK[qp][1], w23.y, db[3]);
            }
#pragma unroll
            for (int qp = 0; qp < 2; qp++) {
                ulonglong2 w01 = __ldg(&WV2[qp * 32 + i4 * 2]);
                ulonglong2 w23 = __ldg(&WV2[qp * 32 + i4 * 2 + 1]);
                FFMA2(accV[qp][0], w01.x, da[0]); FFMA2(accV[qp][0], w01.y, da[1]);
                FFMA2(accV[qp][0], w23.x, da[2]); FFMA2(accV[qp][0], w23.y, da[3]);
                FFMA2(accV[qp][1], w01.x, db[0]); FFMA2(accV[qp][1], w01.y, db[1]);
                FFMA2(accV[qp][1], w23.x, db[2]); FFMA2(accV[qp][1], w23.y, db[3]);
            }
        }
        // K stores (float4, conflict-free)
        {
            int oc0 = pp0 * 2;
            int ob0 = oK + (st * 49 + lane) * 68 + oc0;
            int ob1 = oK + (st * 49 + lane + 32) * 68 + oc0;
#pragma unroll
            for (int g = 0; g < 2; g++) {
                float q0, q1, q2, q3;
                UNPACK2(q0, q1, accK[2 * g][0]); UNPACK2(q2, q3, accK[2 * g + 1][0]);
                *reinterpret_cast<float4*>(&sm[ob0 + g * 4]) = make_float4(q0, q1, q2, q3);
                if (has1) {
                    UNPACK2(q0, q1, accK[2 * g][1]); UNPACK2(q2, q3, accK[2 * g + 1][1]);
                    *reinterpret_cast<float4*>(&sm[ob1 + g * 4]) = make_float4(q0, q1, q2, q3);
                }
            }
        }
        // V stores (float4)
        {
            int oc0 = vp0 * 2;
            int ob0 = oV + (st * 49 + lane) * 36 + oc0;
            int ob1 = oV + (st * 49 + lane + 32) * 36 + oc0;
            float q0, q1, q2, q3;
            UNPACK2(q0, q1, accV[0][0]); UNPACK2(q2, q3, accV[1][0]);
            *reinterpret_cast<float4*>(&sm[ob0]) = make_float4(q0, q1, q2, q3);
            if (has1) {
                UNPACK2(q0, q1, accV[0][1]); UNPACK2(q2, q3, accV[1][1]);
                *reinterpret_cast<float4*>(&sm[ob1]) = make_float4(q0, q1, q2, q3);
            }
        }
    }
    __syncthreads();

    // ---- Phase 3: E = exp(scale * k1 . k2) + transposed copy ET ----
    const float SCALE = 0.17677669529663687f;   // 1/sqrt(32)
    {
        int n  = wid >> 3;
        int w8 = wid & 7;
        int x0 = w8 ? (1 + w8 * 6) : 0;          // 0,7,13,19,25,31,37,43
        int R  = w8 ? 6 : 7;
        float acc[7][2];
#pragma unroll
        for (int xx = 0; xx < 7; xx++) { acc[xx][0] = 0.f; acc[xx][1] = 0.f; }
        const float4* k2a = reinterpret_cast<const float4*>(&sm[oK + (49 + lane) * 68 + n * 32]);
        const float4* k2b = reinterpret_cast<const float4*>(&sm[oK + (49 + lane + 32) * 68 + n * 32]);
#pragma unroll
        for (int c4 = 0; c4 < 8; c4++) {
            float4 e0 = k2a[c4];
            float4 e1 = has1 ? k2b[c4] : make_float4(0.f, 0.f, 0.f, 0.f);
#pragma unroll
            for (int xx = 0; xx < 7; xx++) {
                if (xx < R) {
                    float4 k1 = *reinterpret_cast<const float4*>(
                        &sm[oK + (x0 + xx) * 68 + n * 32 + c4 * 4]);     // broadcast
                    acc[xx][0] += k1.x * e0.x + k1.y * e0.y + k1.z * e0.z + k1.w * e0.w;
                    acc[xx][1] += k1.x * e1.x + k1.y * e1.y + k1.z * e1.z + k1.w * e1.w;
                }
            }
        }
#pragma unroll
        for (int xx = 0; xx < 7; xx++) {
            if (xx < R) {
                int x = x0 + xx;
                float v0 = __expf(acc[xx][0] * SCALE);
                sm[oE + (n * 49 + x) * 52 + lane] = v0;
                sm[oET + (n * 49 + lane) * 52 + x] = v0;
                if (has1) {
                    float v1 = __expf(acc[xx][1] * SCALE);
                    sm[oE + (n * 49 + x) * 52 + lane + 32] = v1;
                    sm[oET + (n * 49 + lane + 32) * 52 + x] = v1;
                }
            }
        }
    }
    __syncthreads();

    // ---- Phase 5: o1 / o2 -> OT[p][i]; sums folded in; 16 warp-tasks ----
    {
        int which = wid >> 3;
        int n  = (wid >> 2) & 1;
        int dg = wid & 3;
        u64 acc[2][2] = {{0ull, 0ull}, {0ull, 0ull}};
        float ssum0 = 0.f, ssum1 = 0.f;
        int erow0 = (which ? oE : oET) + (n * 49 + lane) * 52;
        int erow1 = (which ? oE : oET) + (n * 49 + lane + 32) * 52;
        int vbase = oV + which * 49 * 36 + n * 16 + dg * 4;
#pragma unroll
        for (int k4 = 0; k4 < 12; k4++) {
            float4 e0 = *reinterpret_cast<const float4*>(&sm[erow0 + k4 * 4]);
            float4 e1 = has1 ? *reinterpret_cast<const float4*>(&sm[erow1 + k4 * 4])
                             : make_float4(0.f, 0.f, 0.f, 0.f);
            ssum0 += e0.x + e0.y + e0.z + e0.w;
            ssum1 += e1.x + e1.y + e1.z + e1.w;
            float ea[4] = {e0.x, e0.y, e0.z, e0.w};
            float eb[4] = {e1.x, e1.y, e1.z, e1.w};
#pragma unroll
            for (int k = 0; k < 4; k++) {
                ulonglong2 v2 = *reinterpret_cast<const ulonglong2*>(&sm[vbase + (k4 * 4 + k) * 36]);
                u64 d0, d1;
                DUP2(d0, ea[k]); DUP2(d1, eb[k]);
                FFMA2(acc[0][0], v2.x, d0); FFMA2(acc[1][0], v2.y, d0);
                FFMA2(acc[0][1], v2.x, d1); FFMA2(acc[1][1], v2.y, d1);
            }
        }
        {   // tail k = 48
            float e0 = sm[erow0 + 48];
            float e1 = has1 ? sm[erow1 + 48] : 0.f;
            ssum0 += e0; ssum1 += e1;
            ulonglong2 v2 = *reinterpret_cast<const ulonglong2*>(&sm[vbase + 48 * 36]);
            u64 d0, d1;
            DUP2(d0, e0); DUP2(d1, e1);
            FFMA2(acc[0][0], v2.x, d0); FFMA2(acc[1][0], v2.y, d0);
            FFMA2(acc[0][1], v2.x, d1); FFMA2(acc[1][1], v2.y, d1);
        }
        float f0 = 1.f / ssum0;
        float f1 = has1 ? (1.f / ssum1) : 0.f;
        int col = which * 32 + n * 16 + dg * 4;
        float a0, a1, a2, a3;
        UNPACK2(a0, a1, acc[0][0]); UNPACK2(a2, a3, acc[1][0]);
        *reinterpret_cast<float4*>(&sm[oOT + lane * 68 + col]) =
            make_float4(a0 * f0, a1 * f0, a2 * f0, a3 * f0);
        if (has1) {
            UNPACK2(a0, a1, acc[0][1]); UNPACK2(a2, a3, acc[1][1]);
            *reinterpret_cast<float4*>(&sm[oOT + (lane + 32) * 68 + col]) =
                make_float4(a0 * f1, a1 * f1, a2 * f1, a3 * f1);
        }
    }
    __syncthreads();

    // ---- Phase 6: Out[c][p] = bp[c] + sum_i OT[p][i]*Wp[c][i]; direct gmem scatter ----
    {
        int c0 = wid * 4;
        int cp0 = wid * 2;
        u64 acc[2][2];
#pragma unroll
        for (int j = 0; j < 2; j++) {
            u64 bb; PACK2(bb, __ldg(&bp[c0 + 2 * j]), __ldg(&bp[c0 + 2 * j + 1]));
            acc[j][0] = bb; acc[j][1] = bb;
        }
        const ulonglong2* W2 = reinterpret_cast<const ulonglong2*>(&gWp2[cp0 * 64]);
#pragma unroll
        for (int i4 = 0; i4 < 16; i4++) {
            float4 oa = *reinterpret_cast<const float4*>(&sm[oOT + lane * 68 + i4 * 4]);
            float4 ob = has1 ? *reinterpret_cast<const float4*>(&sm[oOT + (lane + 32) * 68 + i4 * 4])
                             : make_float4(0.f, 0.f, 0.f, 0.f);
            u64 da[4], db[4];
            DUP2(da[0], oa.x); DUP2(da[1], oa.y); DUP2(da[2], oa.z); DUP2(da[3], oa.w);
            DUP2(db[0], ob.x); DUP2(db[1], ob.y); DUP2(db[2], ob.z); DUP2(db[3], ob.w);
#pragma unroll
            for (int j = 0; j < 2; j++) {
                ulonglong2 w01 = __ldg(&W2[j * 32 + i4 * 2]);
                ulonglong2 w23 = __ldg(&W2[j * 32 + i4 * 2 + 1]);
                FFMA2(acc[j][0], w01.x, da[0]); FFMA2(acc[j][0], w01.y, da[1]);
                FFMA2(acc[j][0], w23.x, da[2]); FFMA2(acc[j][0], w23.y, da[3]);
                FFMA2(acc[j][1], w01.x, db[0]); FFMA2(acc[j][1], w01.y, db[1]);
                FFMA2(acc[j][1], w23.x, db[2]); FFMA2(acc[j][1], w23.y, db[3]);
            }
        }
        // direct scatter: p0 = lane, p1 = lane + 32
        {
            int p0 = lane;
            int h0 = si * 21 + (p0 / 7) * 4, w0 = sj * 21 + (p0 % 7) * 4;
            float* o0 = out + ((size_t)(b * 64 + c0) * 256 + h0) * 256 + w0;
            float q0, q1, q2, q3;
            UNPACK2(q0, q1, acc[0][0]); UNPACK2(q2, q3, acc[1][0]);
            o0[0 * 65536] = q0; o0[1 * 65536] = q1; o0[2 * 65536] = q2; o0[3 * 65536] = q3;
            if (has1) {
                int p1 = lane + 32;
                int h1 = si * 21 + (p1 / 7) * 4, w1 = sj * 21 + (p1 % 7) * 4;
                float* o1 = out + ((size_t)(b * 64 + c0) * 256 + h1) * 256 + w1;
                UNPACK2(q0, q1, acc[0][1]); UNPACK2(q2, q3, acc[1][1]);
                o1[0 * 65536] = q0; o1[1 * 65536] = q1; o1[2 * 65536] = q2; o1[3 * 65536] = q3;
            }
        }
    }
}

extern "C" void kernel_launch(void* const* d_in, const int* in_sizes, int n_in,
                              void* d_out, int out_size) {
    const float* x1 = (const float*)d_in[0];
    const float* x2 = (const float*)d_in[1];
    const float* Wk = (const float*)d_in[2];
    const float* bk = (const float*)d_in[3];
    const float* Wv = (const float*)d_in[4];
    const float* bv = (const float*)d_in[5];
    const float* Wp = (const float*)d_in[6];
    const float* bp = (const float*)d_in[7];
    float* out = (float*)d_out;

    repack_kernel<<<32, 256>>>(Wk, Wv, Wp);

    cudaFuncSetAttribute(fused_kernel,
                         cudaFuncAttributeMaxDynamicSharedMemorySize, SMEM_BYTES);
    fused_kernel<<<N_ATTN + N_FILL, BDIM, SMEM_BYTES>>>(x1, x2, Wk, bk, Wv, bv, Wp, bp, out);
}